// round 6
// baseline (speedup 1.0000x reference)
#include <cuda_runtime.h>
#include <cuda_bf16.h>
#include <math.h>
#include <stdint.h>

#define NT 256
#define TB 128
#define KDIM 160
#define RSB 176          // byte stride per row of int8 tiles (16B multiple)

// smem byte offsets
#define OFF_A1  0                  // int8 [128][176]
#define OFF_A2  22528
#define OFF_B   45056              // [buf][copy][64][176] : 4 x 11264
#define OFF_QIN 90112              // float [2][128][4]
#define OFF_B1  94208              // float [2][256]
#define OFF_W2T 96256              // float [2][256][4]
#define OFF_SB  104448             // float [2][256]
#define OFF_SA  106496             // float [128]
#define OFF_B2  107008
#define OFF_TRC 107040
#define OFF_TRS 107232
#define OFF_PP  107424
#define SMEM_BYTES 107440

#define BBUF 22528       // bytes per buffer (2 copies x 11264)
#define BCH  11264       // bytes per copy chunk (64 cols x 176)

// W1 quantized two-level int8, [br][n][RSB]
__device__ __align__(16) int8_t g_W1q1[2][256][RSB];
__device__ __align__(16) int8_t g_W1q2[2][256][RSB];
__device__ float g_sB[2][256];

__device__ __forceinline__ uint32_t smem_u32(const void* p) {
    uint32_t a;
    asm("{ .reg .u64 t; cvta.to.shared.u64 t, %1; cvt.u32.u64 %0, t; }" : "=r"(a) : "l"(p));
    return a;
}
__device__ __forceinline__ void mma_s8(int (&d)[4], const uint32_t (&a)[4],
                                       uint32_t b0, uint32_t b1) {
    asm volatile(
        "mma.sync.aligned.m16n8k32.row.col.s32.s8.s8.s32 "
        "{%0,%1,%2,%3}, {%4,%5,%6,%7}, {%8,%9}, {%0,%1,%2,%3};"
        : "+r"(d[0]), "+r"(d[1]), "+r"(d[2]), "+r"(d[3])
        : "r"(a[0]), "r"(a[1]), "r"(a[2]), "r"(a[3]), "r"(b0), "r"(b1));
}
__device__ __forceinline__ void ldsm4(uint32_t (&r)[4], uint32_t addr) {
    asm volatile("ldmatrix.sync.aligned.m8n8.x4.shared.b16 {%0,%1,%2,%3}, [%4];"
        : "=r"(r[0]), "=r"(r[1]), "=r"(r[2]), "=r"(r[3]) : "r"(addr));
}
#define CPA16(dst, src) asm volatile("cp.async.cg.shared.global [%0], [%1], 16;" :: "r"(dst), "l"(src))
#define CPA_COMMIT()    asm volatile("cp.async.commit_group;")
#define CPA_WAIT1()     asm volatile("cp.async.wait_group 1;")
#define CPA_WAIT0()     asm volatile("cp.async.wait_group 0;")

// ---------------- quantum gates on 16-amplitude register state ----------------
template<int M>
__device__ __forceinline__ void g_ry(float (&ar)[16], float (&ai)[16], float c, float s) {
#pragma unroll
    for (int i = 0; i < 16; i++) if (!(i & M)) {
        const int j = i | M;
        float xr = ar[i], xi = ai[i], yr = ar[j], yi = ai[j];
        ar[i] = c * xr - s * yr;  ai[i] = c * xi - s * yi;
        ar[j] = s * xr + c * yr;  ai[j] = s * xi + c * yi;
    }
}
template<int M>
__device__ __forceinline__ void g_rx(float (&ar)[16], float (&ai)[16], float c, float s) {
#pragma unroll
    for (int i = 0; i < 16; i++) if (!(i & M)) {
        const int j = i | M;
        float xr = ar[i], xi = ai[i], yr = ar[j], yi = ai[j];
        ar[i] = c * xr + s * yi;   ai[i] = c * xi - s * yr;
        ar[j] = s * xi + c * yr;   ai[j] = -s * xr + c * yi;
    }
}
template<int M>
__device__ __forceinline__ void g_rz(float (&ar)[16], float (&ai)[16], float c, float s) {
#pragma unroll
    for (int i = 0; i < 16; i++) if (!(i & M)) {
        const int j = i | M;
        float xr = ar[i], xi = ai[i], yr = ar[j], yi = ai[j];
        ar[i] = c * xr + s * xi;   ai[i] = c * xi - s * xr;
        ar[j] = c * yr - s * yi;   ai[j] = c * yi + s * yr;
    }
}
template<int MC, int MT>
__device__ __forceinline__ void g_cnot(float (&ar)[16], float (&ai)[16]) {
#pragma unroll
    for (int i = 0; i < 16; i++) if ((i & MC) && !(i & MT)) {
        const int j = i | MT;
        float tr = ar[i]; ar[i] = ar[j]; ar[j] = tr;
        float ti = ai[i]; ai[i] = ai[j]; ai[j] = ti;
    }
}

// ---------------- prep: W1 -> two-level int8, one warp per (br, n) ----------------
__global__ void qprep(const float* __restrict__ W1a, const float* __restrict__ W1b) {
    const int wg = blockIdx.x * 8 + (threadIdx.x >> 5);  // 0..511
    const int lane = threadIdx.x & 31;
    const int br = wg >> 8, n = wg & 255;
    const float* W = (br ? W1b : W1a) + (size_t)n * KDIM;
    float v[5];
    float mx = 0.f;
#pragma unroll
    for (int j = 0; j < 5; j++) {
        v[j] = W[lane * 5 + j];
        mx = fmaxf(mx, fabsf(v[j]));
    }
#pragma unroll
    for (int off = 16; off > 0; off >>= 1)
        mx = fmaxf(mx, __shfl_xor_sync(0xffffffffu, mx, off));
    mx = fmaxf(mx, 1e-20f);
    const float inv = 127.f / mx;
    if (lane == 0) g_sB[br][n] = mx * (1.f / 127.f);
#pragma unroll
    for (int j = 0; j < 5; j++) {
        const float f = v[j] * inv;
        const int q1 = __float2int_rn(f);
        int q2 = __float2int_rn((f - (float)q1) * 256.f);
        q2 = max(-127, min(127, q2));
        g_W1q1[br][n][lane * 5 + j] = (int8_t)q1;
        g_W1q2[br][n][lane * 5 + j] = (int8_t)q2;
    }
}

// ---------------- main kernel ----------------
__global__ __launch_bounds__(NT, 2)
void qmain(const float* __restrict__ state, const float* __restrict__ action,
           const float* __restrict__ b1a, const float* __restrict__ W2a, const float* __restrict__ b2a,
           const float* __restrict__ b1b, const float* __restrict__ W2b, const float* __restrict__ b2b,
           const float* __restrict__ qwa, const float* __restrict__ qwb,
           const float* __restrict__ pwa, const float* __restrict__ pba,
           const float* __restrict__ pwb, const float* __restrict__ pbb,
           float* __restrict__ out, int Btot)
{
    extern __shared__ __align__(16) unsigned char smp[];
    float* smf = (float*)smp;
    float* qin = smf + OFF_QIN / 4;
    float* smSA = smf + OFF_SA / 4;
    const uint32_t smb = smem_u32(smp);

    const int tid = threadIdx.x;
    const int lane = tid & 31, w = tid >> 5;
    const int gid = lane >> 2, tig = lane & 3;
    const int wm = w & 3, wn = w >> 2;
    const int m0 = wm * 32, n0 = wn * 32;
    const int rowg0 = blockIdx.x * TB;

    // ---- kick off B loads for pass 0 (buf 0) ----
    {
        const char* s1 = (const char*)&g_W1q1[0][0][0];
        const char* s2 = (const char*)&g_W1q2[0][0][0];
        for (int i = tid; i < BCH / 16; i += NT) {
            CPA16(smb + OFF_B + i * 16, s1 + i * 16);
            CPA16(smb + OFF_B + BCH + i * 16, s2 + i * 16);
        }
        CPA_COMMIT();
    }

    // ---- params into smem ----
    for (int i = tid; i < 512; i += NT)
        smf[OFF_B1 / 4 + i] = ((i >> 8) ? b1b : b1a)[i & 255];
    for (int i = tid; i < 512; i += NT)
        smf[OFF_SB / 4 + i] = g_sB[i >> 8][i & 255];
    for (int i = tid; i < 2048; i += NT) {
        const int br = i >> 10, rem = i & 1023, n = rem >> 2, q = rem & 3;
        smf[OFF_W2T / 4 + i] = (br ? W2b : W2a)[q * 256 + n];
    }
    if (tid < 8)  smf[OFF_B2 / 4 + tid] = ((tid >> 2) ? b2b : b2a)[tid & 3];
    if (tid < 48) {
        const int br = tid / 24, g = tid % 24;
        float sv, cv;
        sincosf(0.5f * (br ? qwb : qwa)[g], &sv, &cv);
        smf[OFF_TRC / 4 + tid] = cv;  smf[OFF_TRS / 4 + tid] = sv;
    }
    if (tid < 4)
        smf[OFF_PP / 4 + tid] = (tid == 0) ? pwa[0] : (tid == 1) ? pba[0]
                               : (tid == 2) ? pwb[0] : pbb[0];
    for (int i = tid; i < 1024; i += NT) qin[i] = 0.f;

    // ---- x -> two-level int8 A tiles (2 threads per row, 80 vals each) ----
    {
        const int r = tid >> 1, hf = tid & 1;
        const float* srow = state  + (size_t)(rowg0 + r) * 128;
        const float* arow = action + (size_t)(rowg0 + r) * 32;
        // pass 1: row max (warms L1)
        float mx = 0.f;
#pragma unroll 5
        for (int i = 0; i < 20; i++) {
            const int k = hf * 80 + i * 4;
            const float4 v = (k < 128) ? *(const float4*)(srow + k)
                                       : *(const float4*)(arow + (k - 128));
            mx = fmaxf(mx, fmaxf(fmaxf(fabsf(v.x), fabsf(v.y)),
                                 fmaxf(fabsf(v.z), fabsf(v.w))));
        }
        mx = fmaxf(mx, __shfl_xor_sync(0xffffffffu, mx, 1));
        mx = fmaxf(mx, 1e-20f);
        const float inv = 127.f / mx;
        if (hf == 0) smSA[r] = mx * (1.f / 127.f);
        // pass 2: quantize (L1 hits)
        char* a1p = (char*)smp + OFF_A1 + r * RSB;
        char* a2p = (char*)smp + OFF_A2 + r * RSB;
#pragma unroll 5
        for (int i = 0; i < 20; i++) {
            const int k = hf * 80 + i * 4;
            const float4 v = (k < 128) ? *(const float4*)(srow + k)
                                       : *(const float4*)(arow + (k - 128));
            const float f[4] = {v.x * inv, v.y * inv, v.z * inv, v.w * inv};
            char q1[4], q2[4];
#pragma unroll
            for (int j = 0; j < 4; j++) {
                const int a = __float2int_rn(f[j]);
                int b = __float2int_rn((f[j] - (float)a) * 256.f);
                b = max(-127, min(127, b));
                q1[j] = (char)a;  q2[j] = (char)b;
            }
            *(char4*)(a1p + k) = make_char4(q1[0], q1[1], q1[2], q1[3]);
            *(char4*)(a2p + k) = make_char4(q2[0], q2[1], q2[2], q2[3]);
        }
    }
    __syncthreads();

    // ---- ldmatrix byte-address bases ----
    const uint32_t aO = (uint32_t)((m0 + (lane & 15)) * RSB + 16 * (lane >> 4));
    const uint32_t a1B0 = smb + OFF_A1 + aO;
    const uint32_t a1B1 = a1B0 + 16u * RSB;
    const uint32_t a2B0 = smb + OFF_A2 + aO;
    const uint32_t a2B1 = a2B0 + 16u * RSB;
    const uint32_t bO0 = (uint32_t)((n0 + 8 * (lane >> 4) + (lane & 7)) * RSB
                                    + 16 * ((lane >> 3) & 1));
    const uint32_t bO1 = bO0 + 16u * RSB;

    // deferred W2 partials (h0 rows), flushed per branch
    float p0[4] = {0.f, 0.f, 0.f, 0.f}, p1[4] = {0.f, 0.f, 0.f, 0.f};

#pragma unroll 1
    for (int pass = 0; pass < 8; pass++) {
        const int br = pass >> 2, chunk = pass & 3;
        const int nbase = chunk * 64;
        const int buf = pass & 1;

        if (pass < 7) {
            const int pN = pass + 1;
            const char* s1 = (const char*)&g_W1q1[pN >> 2][(pN & 3) * 64][0];
            const char* s2 = (const char*)&g_W1q2[pN >> 2][(pN & 3) * 64][0];
            const uint32_t dst = smb + OFF_B + (uint32_t)(pN & 1) * BBUF;
            for (int i = tid; i < BCH / 16; i += NT) {
                CPA16(dst + i * 16, s1 + i * 16);
                CPA16(dst + BCH + i * 16, s2 + i * 16);
            }
            CPA_COMMIT();
            CPA_WAIT1();
        } else {
            CPA_WAIT0();
        }
        __syncthreads();

        const uint32_t b1B = smb + OFF_B + (uint32_t)buf * BBUF;
        const uint32_t b2B = b1B + BCH;

        int accM[2][4][4], accC[2][4][4];
#pragma unroll
        for (int mf = 0; mf < 2; mf++)
#pragma unroll
            for (int nf = 0; nf < 4; nf++)
#pragma unroll
                for (int c = 0; c < 4; c++) { accM[mf][nf][c] = 0; accC[mf][nf][c] = 0; }

#pragma unroll
        for (int ks = 0; ks < 5; ks++) {
            const uint32_t kb = (uint32_t)(ks * 32);
            uint32_t a1f[2][4], a2f[2][4], b1f[2][4], b2f[2][4];
            ldsm4(a1f[0], a1B0 + kb);
            ldsm4(a1f[1], a1B1 + kb);
            ldsm4(a2f[0], a2B0 + kb);
            ldsm4(a2f[1], a2B1 + kb);
            ldsm4(b1f[0], b1B + bO0 + kb);
            ldsm4(b1f[1], b1B + bO1 + kb);
            ldsm4(b2f[0], b2B + bO0 + kb);
            ldsm4(b2f[1], b2B + bO1 + kb);
            // term 0: A1*B1 -> accM
#pragma unroll
            for (int g = 0; g < 2; g++)
#pragma unroll
                for (int h = 0; h < 2; h++)
#pragma unroll
                    for (int mf = 0; mf < 2; mf++)
                        mma_s8(accM[mf][g * 2 + h], a1f[mf], b1f[g][h * 2], b1f[g][h * 2 + 1]);
            // term 1: A1*B2 -> accC
#pragma unroll
            for (int g = 0; g < 2; g++)
#pragma unroll
                for (int h = 0; h < 2; h++)
#pragma unroll
                    for (int mf = 0; mf < 2; mf++)
                        mma_s8(accC[mf][g * 2 + h], a1f[mf], b2f[g][h * 2], b2f[g][h * 2 + 1]);
            // term 2: A2*B1 -> accC
#pragma unroll
            for (int g = 0; g < 2; g++)
#pragma unroll
                for (int h = 0; h < 2; h++)
#pragma unroll
                    for (int mf = 0; mf < 2; mf++)
                        mma_s8(accC[mf][g * 2 + h], a2f[mf], b1f[g][h * 2], b1f[g][h * 2 + 1]);
        }

        // ---- dequant + bias + relu + W2 contraction ----
        const float* b1s = smf + OFF_B1 / 4 + br * 256;
        const float* w2t = smf + OFF_W2T / 4 + br * 1024;
        const float* sBp = smf + OFF_SB / 4 + br * 256;
#pragma unroll
        for (int mf = 0; mf < 2; mf++) {
            const float sA0 = smSA[m0 + mf * 16 + gid];
            const float sA1 = smSA[m0 + mf * 16 + gid + 8];
            float* pp = mf ? p1 : p0;
            float s4[4] = {0.f, 0.f, 0.f, 0.f};
#pragma unroll
            for (int nf = 0; nf < 4; nf++)
#pragma unroll
                for (int c = 0; c < 2; c++) {
                    const int gcol = nbase + n0 + nf * 8 + 2 * tig + c;
                    const float sc = sBp[gcol];
                    const float bb = b1s[gcol];
                    const float f0 = (float)accM[mf][nf][c]
                                   + (float)accC[mf][nf][c] * 0.00390625f;
                    const float f1 = (float)accM[mf][nf][2 + c]
                                   + (float)accC[mf][nf][2 + c] * 0.00390625f;
                    const float h0 = fmaxf(f0 * (sA0 * sc) + bb, 0.f);
                    const float h1 = fmaxf(f1 * (sA1 * sc) + bb, 0.f);
                    const float4 wv = *(const float4*)(w2t + gcol * 4);
                    pp[0] = fmaf(h0, wv.x, pp[0]);  pp[1] = fmaf(h0, wv.y, pp[1]);
                    pp[2] = fmaf(h0, wv.z, pp[2]);  pp[3] = fmaf(h0, wv.w, pp[3]);
                    s4[0] = fmaf(h1, wv.x, s4[0]);  s4[1] = fmaf(h1, wv.y, s4[1]);
                    s4[2] = fmaf(h1, wv.z, s4[2]);  s4[3] = fmaf(h1, wv.w, s4[3]);
                }
#pragma unroll
            for (int off = 1; off <= 2; off <<= 1)
#pragma unroll
                for (int j = 0; j < 4; j++)
                    s4[j] += __shfl_xor_sync(0xffffffffu, s4[j], off);
            if (tig == 0) {
                float* qdst = qin + ((br << 7) + m0 + mf * 16 + gid + 8) * 4;
#pragma unroll
                for (int j = 0; j < 4; j++) atomicAdd(qdst + j, s4[j]);
            }
        }

        if (chunk == 3) {
#pragma unroll
            for (int off = 1; off <= 2; off <<= 1)
#pragma unroll
                for (int j = 0; j < 4; j++) {
                    p0[j] += __shfl_xor_sync(0xffffffffu, p0[j], off);
                    p1[j] += __shfl_xor_sync(0xffffffffu, p1[j], off);
                }
            if (tig == 0) {
                float* q0 = qin + ((br << 7) + m0 + gid) * 4;
                float* q1 = qin + ((br << 7) + m0 + 16 + gid) * 4;
#pragma unroll
                for (int j = 0; j < 4; j++) {
                    atomicAdd(q0 + j, p0[j]);
                    atomicAdd(q1 + j, p1[j]);
                }
            }
#pragma unroll
            for (int j = 0; j < 4; j++) { p0[j] = 0.f; p1[j] = 0.f; }
        }

        __syncthreads();
    }
    __syncthreads();

    // ---- quantum circuit: 1 row/thread, 128 rows x 2 branches ----
    {
        const int br = tid >> 7, row = tid & 127;
        const float* b2s = smf + OFF_B2 / 4 + br * 4;
        const float* trc = smf + OFF_TRC / 4 + br * 24;
        const float* trs = smf + OFF_TRS / 4 + br * 24;
        const float pw = smf[OFF_PP / 4 + br * 2];
        const float pb = smf[OFF_PP / 4 + br * 2 + 1];
        const float* qv = qin + ((br << 7) + row) * 4;
        const float th[4] = {qv[0] + b2s[0], qv[1] + b2s[1], qv[2] + b2s[2], qv[3] + b2s[3]};

        float ar[16], ai[16];
#pragma unroll
        for (int i = 0; i < 16; i++) { ar[i] = 0.f; ai[i] = 0.f; }
        ar[0] = 1.f;

        float s0, c0;
        sincosf(0.5f * th[0], &s0, &c0);  g_ry<8>(ar, ai, c0, s0);
        sincosf(0.5f * th[1], &s0, &c0);  g_ry<4>(ar, ai, c0, s0);
        sincosf(0.5f * th[2], &s0, &c0);  g_ry<2>(ar, ai, c0, s0);
        sincosf(0.5f * th[3], &s0, &c0);  g_ry<1>(ar, ai, c0, s0);

#pragma unroll
        for (int l = 0; l < 2; l++) {
            const int lb = l * 12;
            g_rx<8>(ar, ai, trc[lb + 0],  trs[lb + 0]);
            g_ry<8>(ar, ai, trc[lb + 1],  trs[lb + 1]);
            g_rz<8>(ar, ai, trc[lb + 2],  trs[lb + 2]);
            g_rx<4>(ar, ai, trc[lb + 3],  trs[lb + 3]);
            g_ry<4>(ar, ai, trc[lb + 4],  trs[lb + 4]);
            g_rz<4>(ar, ai, trc[lb + 5],  trs[lb + 5]);
            g_rx<2>(ar, ai, trc[lb + 6],  trs[lb + 6]);
            g_ry<2>(ar, ai, trc[lb + 7],  trs[lb + 7]);
            g_rz<2>(ar, ai, trc[lb + 8],  trs[lb + 8]);
            g_rx<1>(ar, ai, trc[lb + 9],  trs[lb + 9]);
            g_ry<1>(ar, ai, trc[lb + 10], trs[lb + 10]);
            g_rz<1>(ar, ai, trc[lb + 11], trs[lb + 11]);
            g_cnot<8, 4>(ar, ai);
            g_cnot<4, 2>(ar, ai);
            g_cnot<2, 1>(ar, ai);
            g_cnot<1, 8>(ar, ai);
        }

        float ev = 0.f;
#pragma unroll
        for (int i = 0; i < 16; i++) {
            const float p = ar[i] * ar[i] + ai[i] * ai[i];
            ev += (i & 8) ? -p : p;
        }
        out[(size_t)br * Btot + rowg0 + row] = fmaf(ev, pw, pb);
    }
}

extern "C" void kernel_launch(void* const* d_in, const int* in_sizes, int n_in,
                              void* d_out, int out_size)
{
    const int Btot = in_sizes[0] / 128;
    static bool attr_set = false;
    if (!attr_set) {
        cudaFuncSetAttribute(qmain, cudaFuncAttributeMaxDynamicSharedMemorySize, SMEM_BYTES);
        attr_set = true;
    }
    qprep<<<64, 256>>>((const float*)d_in[2], (const float*)d_in[6]);
    qmain<<<Btot / TB, NT, SMEM_BYTES>>>(
        (const float*)d_in[0],  (const float*)d_in[1],
        (const float*)d_in[3],  (const float*)d_in[4],  (const float*)d_in[5],
        (const float*)d_in[7],  (const float*)d_in[8],  (const float*)d_in[9],
        (const float*)d_in[10], (const float*)d_in[11],
        (const float*)d_in[12], (const float*)d_in[13],
        (const float*)d_in[14], (const float*)d_in[15],
        (float*)d_out, Btot);
}

// round 7
// speedup vs baseline: 3.0533x; 3.0533x over previous
#include <cuda_runtime.h>
#include <cuda_fp16.h>
#include <math.h>
#include <stdint.h>

#define NT 256
#define TB 128
#define KDIM 160
#define RS 168           // k-stride (elements)

// smem byte offsets
#define OFF_A   0                 // fp16 [128][168] = 43008
#define OFF_B   43008             // [buf][hi/lo][32][168] fp16 : 4 x 10752
#define OFF_QIN 86016             // float [2][128][4]
#define OFF_B1  90112             // float [2][256]
#define OFF_W2T 92160             // float [2][256][4]
#define OFF_B2  100352
#define OFF_TRC 100384
#define OFF_TRS 100576
#define OFF_PP  100768
#define SMEM_BYTES 100784

#define BCH  10752       // bytes per (hi or lo) N=32 chunk
#define BBUF 21504       // bytes per buffer (hi+lo)

// W1 pre-split into fp16 hi/lo, [br][n][RS]
__device__ __align__(16) __half g_W1h[2][256][RS];
__device__ __align__(16) __half g_W1l[2][256][RS];

__device__ __forceinline__ uint32_t smem_u32(const void* p) {
    uint32_t a;
    asm("{ .reg .u64 t; cvta.to.shared.u64 t, %1; cvt.u32.u64 %0, t; }" : "=r"(a) : "l"(p));
    return a;
}
__device__ __forceinline__ void mma_f16(float (&d)[4], const uint32_t (&a)[4],
                                        uint32_t b0, uint32_t b1) {
    asm volatile(
        "mma.sync.aligned.m16n8k16.row.col.f32.f16.f16.f32 "
        "{%0,%1,%2,%3}, {%4,%5,%6,%7}, {%8,%9}, {%0,%1,%2,%3};"
        : "+f"(d[0]), "+f"(d[1]), "+f"(d[2]), "+f"(d[3])
        : "r"(a[0]), "r"(a[1]), "r"(a[2]), "r"(a[3]), "r"(b0), "r"(b1));
}
__device__ __forceinline__ void ldsm4(uint32_t (&r)[4], uint32_t addr) {
    asm volatile("ldmatrix.sync.aligned.m8n8.x4.shared.b16 {%0,%1,%2,%3}, [%4];"
        : "=r"(r[0]), "=r"(r[1]), "=r"(r[2]), "=r"(r[3]) : "r"(addr));
}
#define CPA16(dst, src) asm volatile("cp.async.cg.shared.global [%0], [%1], 16;" :: "r"(dst), "l"(src))
#define CPA_COMMIT()    asm volatile("cp.async.commit_group;")
#define CPA_WAIT1()     asm volatile("cp.async.wait_group 1;")
#define CPA_WAIT0()     asm volatile("cp.async.wait_group 0;")

// ---------------- quantum gates on 16-amplitude register state ----------------
template<int M>
__device__ __forceinline__ void g_ry(float (&ar)[16], float (&ai)[16], float c, float s) {
#pragma unroll
    for (int i = 0; i < 16; i++) if (!(i & M)) {
        const int j = i | M;
        float xr = ar[i], xi = ai[i], yr = ar[j], yi = ai[j];
        ar[i] = c * xr - s * yr;  ai[i] = c * xi - s * yi;
        ar[j] = s * xr + c * yr;  ai[j] = s * xi + c * yi;
    }
}
template<int M>
__device__ __forceinline__ void g_rx(float (&ar)[16], float (&ai)[16], float c, float s) {
#pragma unroll
    for (int i = 0; i < 16; i++) if (!(i & M)) {
        const int j = i | M;
        float xr = ar[i], xi = ai[i], yr = ar[j], yi = ai[j];
        ar[i] = c * xr + s * yi;   ai[i] = c * xi - s * yr;
        ar[j] = s * xi + c * yr;   ai[j] = -s * xr + c * yi;
    }
}
template<int M>
__device__ __forceinline__ void g_rz(float (&ar)[16], float (&ai)[16], float c, float s) {
#pragma unroll
    for (int i = 0; i < 16; i++) if (!(i & M)) {
        const int j = i | M;
        float xr = ar[i], xi = ai[i], yr = ar[j], yi = ai[j];
        ar[i] = c * xr + s * xi;   ai[i] = c * xi - s * xr;
        ar[j] = c * yr - s * yi;   ai[j] = c * yi + s * yr;
    }
}
template<int MC, int MT>
__device__ __forceinline__ void g_cnot(float (&ar)[16], float (&ai)[16]) {
#pragma unroll
    for (int i = 0; i < 16; i++) if ((i & MC) && !(i & MT)) {
        const int j = i | MT;
        float tr = ar[i]; ar[i] = ar[j]; ar[j] = tr;
        float ti = ai[i]; ai[i] = ai[j]; ai[j] = ti;
    }
}

// ---------------- prep: W1 -> fp16 hi/lo ----------------
__global__ void qprep(const float* __restrict__ W1a, const float* __restrict__ W1b) {
    const int t = blockIdx.x * 256 + threadIdx.x;    // 0..20479
    const int br = t / 10240;
    const int rem = t % 10240;
    const int n = rem / 40, k4 = rem % 40;
    const float4 v = *(const float4*)((br ? W1b : W1a) + (size_t)n * KDIM + k4 * 4);
    const float vals[4] = {v.x, v.y, v.z, v.w};
#pragma unroll
    for (int j = 0; j < 4; j++) {
        const __half h = __float2half_rn(vals[j]);
        g_W1h[br][n][k4 * 4 + j] = h;
        g_W1l[br][n][k4 * 4 + j] = __float2half_rn(vals[j] - __half2float(h));
    }
}

// ---------------- main kernel ----------------
__global__ __launch_bounds__(NT, 2)
void qmain(const float* __restrict__ state, const float* __restrict__ action,
           const float* __restrict__ b1a, const float* __restrict__ W2a, const float* __restrict__ b2a,
           const float* __restrict__ b1b, const float* __restrict__ W2b, const float* __restrict__ b2b,
           const float* __restrict__ qwa, const float* __restrict__ qwb,
           const float* __restrict__ pwa, const float* __restrict__ pba,
           const float* __restrict__ pwb, const float* __restrict__ pbb,
           float* __restrict__ out, int Btot)
{
    extern __shared__ __align__(16) unsigned char smp[];
    float* smf = (float*)smp;
    __half* Ah = (__half*)(smp + OFF_A);
    float* qin = smf + OFF_QIN / 4;
    const uint32_t smb = smem_u32(smp);

    const int tid = threadIdx.x;
    const int lane = tid & 31, w = tid >> 5;
    const int gid = lane >> 2, tig = lane & 3;
    const int wm = w & 3, wn = w >> 2;
    const int m0 = wm * 32, n0 = wn * 16;
    const int rowg0 = blockIdx.x * TB;

    // ---- kick off B loads for pass 0 (buf 0) ----
    {
        const char* sH = (const char*)&g_W1h[0][0][0];
        const char* sL = (const char*)&g_W1l[0][0][0];
        for (int i = tid; i < BCH / 16; i += NT) {
            CPA16(smb + OFF_B + i * 16, sH + i * 16);
            CPA16(smb + OFF_B + BCH + i * 16, sL + i * 16);
        }
        CPA_COMMIT();
    }

    // ---- params into smem ----
    for (int i = tid; i < 512; i += NT)
        smf[OFF_B1 / 4 + i] = ((i >> 8) ? b1b : b1a)[i & 255];
    for (int i = tid; i < 2048; i += NT) {
        const int br = i >> 10, rem = i & 1023, n = rem >> 2, q = rem & 3;
        smf[OFF_W2T / 4 + i] = (br ? W2b : W2a)[q * 256 + n];
    }
    if (tid < 8)  smf[OFF_B2 / 4 + tid] = ((tid >> 2) ? b2b : b2a)[tid & 3];
    if (tid < 48) {
        const int br = tid / 24, g = tid % 24;
        float sv, cv;
        sincosf(0.5f * (br ? qwb : qwa)[g], &sv, &cv);
        smf[OFF_TRC / 4 + tid] = cv;  smf[OFF_TRS / 4 + tid] = sv;
    }
    if (tid < 4)
        smf[OFF_PP / 4 + tid] = (tid == 0) ? pwa[0] : (tid == 1) ? pba[0]
                               : (tid == 2) ? pwb[0] : pbb[0];
    for (int i = tid; i < 1024; i += NT) qin[i] = 0.f;

    // ---- x -> fp16 A tile [row][k], stride RS ----
    {
        const int r = tid >> 1, hf = tid & 1;
        const float* srow = state  + (size_t)(rowg0 + r) * 128;
        const float* arow = action + (size_t)(rowg0 + r) * 32;
#pragma unroll 5
        for (int i = 0; i < 20; i++) {
            const int k = hf * 80 + i * 4;
            const float4 v = (k < 128) ? *(const float4*)(srow + k)
                                       : *(const float4*)(arow + (k - 128));
            *(__half2*)(Ah + r * RS + k)     = __floats2half2_rn(v.x, v.y);
            *(__half2*)(Ah + r * RS + k + 2) = __floats2half2_rn(v.z, v.w);
        }
    }
    __syncthreads();

    // ---- ldmatrix byte-address bases ----
    const uint32_t aB0 = smb + OFF_A
        + (uint32_t)((m0 + (lane & 15)) * RS + 8 * (lane >> 4)) * 2;
    const uint32_t aB1 = aB0 + 16u * RS * 2;
    const uint32_t bO = (uint32_t)((n0 + 8 * (lane >> 4) + (lane & 7)) * RS
                                   + 8 * ((lane >> 3) & 1)) * 2;

    // deferred W2 partials: P[0]=mf0 row, P[1]=mf0 row+8, P[2]=mf1 row, P[3]=mf1 row+8
    float P[4][4];
#pragma unroll
    for (int a = 0; a < 4; a++)
#pragma unroll
        for (int j = 0; j < 4; j++) P[a][j] = 0.f;

#pragma unroll 1
    for (int pass = 0; pass < 16; pass++) {
        const int br = pass >> 3, chunk = pass & 7;
        const int nbase = chunk * 32;
        const int buf = pass & 1;

        // prefetch next chunk into other buffer
        if (pass < 15) {
            const int pN = pass + 1;
            const char* sH = (const char*)&g_W1h[pN >> 3][(pN & 7) * 32][0];
            const char* sL = (const char*)&g_W1l[pN >> 3][(pN & 7) * 32][0];
            const uint32_t dst = smb + OFF_B + (uint32_t)(pN & 1) * BBUF;
            for (int i = tid; i < BCH / 16; i += NT) {
                CPA16(dst + i * 16, sH + i * 16);
                CPA16(dst + BCH + i * 16, sL + i * 16);
            }
            CPA_COMMIT();
            CPA_WAIT1();
        } else {
            CPA_WAIT0();
        }
        __syncthreads();

        const uint32_t bhB = smb + OFF_B + (uint32_t)buf * BBUF;
        const uint32_t blB = bhB + BCH;

        float acc[2][2][4];
#pragma unroll
        for (int mf = 0; mf < 2; mf++)
#pragma unroll
            for (int nf = 0; nf < 2; nf++)
#pragma unroll
                for (int c = 0; c < 4; c++) acc[mf][nf][c] = 0.f;

#pragma unroll
        for (int ks = 0; ks < 10; ks++) {
            const uint32_t kb = (uint32_t)(ks * 32);   // 16 elem * 2B
            uint32_t af[2][4], bh[4], bl[4];
            ldsm4(af[0], aB0 + kb);
            ldsm4(af[1], aB1 + kb);
            ldsm4(bh, bhB + bO + kb);
            ldsm4(bl, blB + bO + kb);
#pragma unroll
            for (int t = 0; t < 2; t++)
#pragma unroll
                for (int nf = 0; nf < 2; nf++)
#pragma unroll
                    for (int mf = 0; mf < 2; mf++) {
                        const uint32_t b0 = t ? bl[nf * 2]     : bh[nf * 2];
                        const uint32_t b1 = t ? bl[nf * 2 + 1] : bh[nf * 2 + 1];
                        mma_f16(acc[mf][nf], af[mf], b0, b1);
                    }
        }

        // ---- bias + relu + W2 contraction into register partials ----
        const float* b1s = smf + OFF_B1 / 4 + br * 256;
        const float* w2t = smf + OFF_W2T / 4 + br * 1024;
#pragma unroll
        for (int mf = 0; mf < 2; mf++)
#pragma unroll
            for (int nf = 0; nf < 2; nf++)
#pragma unroll
                for (int c = 0; c < 2; c++) {
                    const int gcol = nbase + n0 + nf * 8 + 2 * tig + c;
                    const float bb = b1s[gcol];
                    const float4 wv = *(const float4*)(w2t + gcol * 4);
                    const float h0 = fmaxf(acc[mf][nf][c] + bb, 0.f);
                    const float h1 = fmaxf(acc[mf][nf][2 + c] + bb, 0.f);
                    float* pa = P[mf * 2];
                    float* pb2 = P[mf * 2 + 1];
                    pa[0] = fmaf(h0, wv.x, pa[0]);   pa[1] = fmaf(h0, wv.y, pa[1]);
                    pa[2] = fmaf(h0, wv.z, pa[2]);   pa[3] = fmaf(h0, wv.w, pa[3]);
                    pb2[0] = fmaf(h1, wv.x, pb2[0]); pb2[1] = fmaf(h1, wv.y, pb2[1]);
                    pb2[2] = fmaf(h1, wv.z, pb2[2]); pb2[3] = fmaf(h1, wv.w, pb2[3]);
                }

        // flush at branch boundary
        if (chunk == 7) {
#pragma unroll
            for (int off = 1; off <= 2; off <<= 1)
#pragma unroll
                for (int a = 0; a < 4; a++)
#pragma unroll
                    for (int j = 0; j < 4; j++)
                        P[a][j] += __shfl_xor_sync(0xffffffffu, P[a][j], off);
            if (tig == 0) {
                const int rows[4] = {m0 + gid, m0 + gid + 8, m0 + 16 + gid, m0 + 24 + gid};
#pragma unroll
                for (int a = 0; a < 4; a++) {
                    float* qdst = qin + ((br << 7) + rows[a]) * 4;
#pragma unroll
                    for (int j = 0; j < 4; j++) atomicAdd(qdst + j, P[a][j]);
                }
            }
#pragma unroll
            for (int a = 0; a < 4; a++)
#pragma unroll
                for (int j = 0; j < 4; j++) P[a][j] = 0.f;
        }

        __syncthreads();   // all reads of buf done before overwrite
    }
    __syncthreads();

    // ---- quantum circuit: 1 row/thread, 128 rows x 2 branches ----
    {
        const int br = tid >> 7, row = tid & 127;
        const float* b2s = smf + OFF_B2 / 4 + br * 4;
        const float* trc = smf + OFF_TRC / 4 + br * 24;
        const float* trs = smf + OFF_TRS / 4 + br * 24;
        const float pw = smf[OFF_PP / 4 + br * 2];
        const float pb = smf[OFF_PP / 4 + br * 2 + 1];
        const float* qv = qin + ((br << 7) + row) * 4;
        const float th[4] = {qv[0] + b2s[0], qv[1] + b2s[1], qv[2] + b2s[2], qv[3] + b2s[3]};

        float ar[16], ai[16];
#pragma unroll
        for (int i = 0; i < 16; i++) { ar[i] = 0.f; ai[i] = 0.f; }
        ar[0] = 1.f;

        float s0, c0;
        sincosf(0.5f * th[0], &s0, &c0);  g_ry<8>(ar, ai, c0, s0);
        sincosf(0.5f * th[1], &s0, &c0);  g_ry<4>(ar, ai, c0, s0);
        sincosf(0.5f * th[2], &s0, &c0);  g_ry<2>(ar, ai, c0, s0);
        sincosf(0.5f * th[3], &s0, &c0);  g_ry<1>(ar, ai, c0, s0);

#pragma unroll
        for (int l = 0; l < 2; l++) {
            const int lb = l * 12;
            g_rx<8>(ar, ai, trc[lb + 0],  trs[lb + 0]);
            g_ry<8>(ar, ai, trc[lb + 1],  trs[lb + 1]);
            g_rz<8>(ar, ai, trc[lb + 2],  trs[lb + 2]);
            g_rx<4>(ar, ai, trc[lb + 3],  trs[lb + 3]);
            g_ry<4>(ar, ai, trc[lb + 4],  trs[lb + 4]);
            g_rz<4>(ar, ai, trc[lb + 5],  trs[lb + 5]);
            g_rx<2>(ar, ai, trc[lb + 6],  trs[lb + 6]);
            g_ry<2>(ar, ai, trc[lb + 7],  trs[lb + 7]);
            g_rz<2>(ar, ai, trc[lb + 8],  trs[lb + 8]);
            g_rx<1>(ar, ai, trc[lb + 9],  trs[lb + 9]);
            g_ry<1>(ar, ai, trc[lb + 10], trs[lb + 10]);
            g_rz<1>(ar, ai, trc[lb + 11], trs[lb + 11]);
            g_cnot<8, 4>(ar, ai);
            g_cnot<4, 2>(ar, ai);
            g_cnot<2, 1>(ar, ai);
            g_cnot<1, 8>(ar, ai);
        }

        float ev = 0.f;
#pragma unroll
        for (int i = 0; i < 16; i++) {
            const float p = ar[i] * ar[i] + ai[i] * ai[i];
            ev += (i & 8) ? -p : p;
        }
        out[(size_t)br * Btot + rowg0 + row] = fmaf(ev, pw, pb);
    }
}

extern "C" void kernel_launch(void* const* d_in, const int* in_sizes, int n_in,
                              void* d_out, int out_size)
{
    const int Btot = in_sizes[0] / 128;
    static bool attr_set = false;
    if (!attr_set) {
        cudaFuncSetAttribute(qmain, cudaFuncAttributeMaxDynamicSharedMemorySize, SMEM_BYTES);
        attr_set = true;
    }
    qprep<<<80, 256>>>((const float*)d_in[2], (const float*)d_in[6]);
    qmain<<<Btot / TB, NT, SMEM_BYTES>>>(
        (const float*)d_in[0],  (const float*)d_in[1],
        (const float*)d_in[3],  (const float*)d_in[4],  (const float*)d_in[5],
        (const float*)d_in[7],  (const float*)d_in[8],  (const float*)d_in[9],
        (const float*)d_in[10], (const float*)d_in[11],
        (const float*)d_in[12], (const float*)d_in[13],
        (const float*)d_in[14], (const float*)d_in[15],
        (float*)d_out, Btot);
}

// round 8
// speedup vs baseline: 4.1638x; 1.3637x over previous
#include <cuda_runtime.h>
#include <cuda_fp16.h>
#include <math.h>
#include <stdint.h>

#define NT 256
#define TB 128
#define KDIM 160
#define RS 168           // k-stride (elements)

// smem byte offsets
#define OFF_A   0                 // fp16 [128][168] = 43008
#define OFF_B   43008             // [buf][64][168] fp16 : 2 x 21504
#define OFF_QIN 86016             // float [2][128][4]
#define OFF_B1  90112             // float [2][256]
#define OFF_W2T 92160             // float [2][256][4]
#define OFF_B2  100352
#define OFF_TRC 100384
#define OFF_TRS 100576
#define OFF_PP  100768
#define SMEM_BYTES 100784

#define BCH  21504       // bytes per N=64 chunk (64 x 168 x 2B)

// W1 as fp16, [br][n][RS]
__device__ __align__(16) __half g_W1h[2][256][RS];

__device__ __forceinline__ uint32_t smem_u32(const void* p) {
    uint32_t a;
    asm("{ .reg .u64 t; cvta.to.shared.u64 t, %1; cvt.u32.u64 %0, t; }" : "=r"(a) : "l"(p));
    return a;
}
__device__ __forceinline__ void mma_f16(float (&d)[4], const uint32_t (&a)[4],
                                        uint32_t b0, uint32_t b1) {
    asm volatile(
        "mma.sync.aligned.m16n8k16.row.col.f32.f16.f16.f32 "
        "{%0,%1,%2,%3}, {%4,%5,%6,%7}, {%8,%9}, {%0,%1,%2,%3};"
        : "+f"(d[0]), "+f"(d[1]), "+f"(d[2]), "+f"(d[3])
        : "r"(a[0]), "r"(a[1]), "r"(a[2]), "r"(a[3]), "r"(b0), "r"(b1));
}
__device__ __forceinline__ void ldsm4(uint32_t (&r)[4], uint32_t addr) {
    asm volatile("ldmatrix.sync.aligned.m8n8.x4.shared.b16 {%0,%1,%2,%3}, [%4];"
        : "=r"(r[0]), "=r"(r[1]), "=r"(r[2]), "=r"(r[3]) : "r"(addr));
}
#define CPA16(dst, src) asm volatile("cp.async.cg.shared.global [%0], [%1], 16;" :: "r"(dst), "l"(src))
#define CPA_COMMIT()    asm volatile("cp.async.commit_group;")
#define CPA_WAIT1()     asm volatile("cp.async.wait_group 1;")
#define CPA_WAIT0()     asm volatile("cp.async.wait_group 0;")

// ---------------- quantum gates on 16-amplitude register state ----------------
template<int M>
__device__ __forceinline__ void g_ry(float (&ar)[16], float (&ai)[16], float c, float s) {
#pragma unroll
    for (int i = 0; i < 16; i++) if (!(i & M)) {
        const int j = i | M;
        float xr = ar[i], xi = ai[i], yr = ar[j], yi = ai[j];
        ar[i] = c * xr - s * yr;  ai[i] = c * xi - s * yi;
        ar[j] = s * xr + c * yr;  ai[j] = s * xi + c * yi;
    }
}
template<int M>
__device__ __forceinline__ void g_rx(float (&ar)[16], float (&ai)[16], float c, float s) {
#pragma unroll
    for (int i = 0; i < 16; i++) if (!(i & M)) {
        const int j = i | M;
        float xr = ar[i], xi = ai[i], yr = ar[j], yi = ai[j];
        ar[i] = c * xr + s * yi;   ai[i] = c * xi - s * yr;
        ar[j] = s * xi + c * yr;   ai[j] = -s * xr + c * yi;
    }
}
template<int M>
__device__ __forceinline__ void g_rz(float (&ar)[16], float (&ai)[16], float c, float s) {
#pragma unroll
    for (int i = 0; i < 16; i++) if (!(i & M)) {
        const int j = i | M;
        float xr = ar[i], xi = ai[i], yr = ar[j], yi = ai[j];
        ar[i] = c * xr + s * xi;   ai[i] = c * xi - s * xr;
        ar[j] = c * yr - s * yi;   ai[j] = c * yi + s * yr;
    }
}
template<int MC, int MT>
__device__ __forceinline__ void g_cnot(float (&ar)[16], float (&ai)[16]) {
#pragma unroll
    for (int i = 0; i < 16; i++) if ((i & MC) && !(i & MT)) {
        const int j = i | MT;
        float tr = ar[i]; ar[i] = ar[j]; ar[j] = tr;
        float ti = ai[i]; ai[i] = ai[j]; ai[j] = ti;
    }
}

// ---------------- prep: W1 -> fp16 ----------------
__global__ void qprep(const float* __restrict__ W1a, const float* __restrict__ W1b) {
    const int t = blockIdx.x * 256 + threadIdx.x;    // 0..20479
    const int br = t / 10240;
    const int rem = t % 10240;
    const int n = rem / 40, k4 = rem % 40;
    const float4 v = *(const float4*)((br ? W1b : W1a) + (size_t)n * KDIM + k4 * 4);
    __half2* dst = (__half2*)&g_W1h[br][n][k4 * 4];
    dst[0] = __floats2half2_rn(v.x, v.y);
    dst[1] = __floats2half2_rn(v.z, v.w);
}

// ---------------- main kernel ----------------
__global__ __launch_bounds__(NT, 2)
void qmain(const float* __restrict__ state, const float* __restrict__ action,
           const float* __restrict__ b1a, const float* __restrict__ W2a, const float* __restrict__ b2a,
           const float* __restrict__ b1b, const float* __restrict__ W2b, const float* __restrict__ b2b,
           const float* __restrict__ qwa, const float* __restrict__ qwb,
           const float* __restrict__ pwa, const float* __restrict__ pba,
           const float* __restrict__ pwb, const float* __restrict__ pbb,
           float* __restrict__ out, int Btot)
{
    extern __shared__ __align__(16) unsigned char smp[];
    float* smf = (float*)smp;
    __half* Ah = (__half*)(smp + OFF_A);
    float* qin = smf + OFF_QIN / 4;
    const uint32_t smb = smem_u32(smp);

    const int tid = threadIdx.x;
    const int lane = tid & 31, w = tid >> 5;
    const int gid = lane >> 2, tig = lane & 3;
    const int wm = w & 3, wn = w >> 2;
    const int m0 = wm * 32, n0 = wn * 32;
    const int rowg0 = blockIdx.x * TB;

    // ---- kick off B load for pass 0 (buf 0) ----
    {
        const char* sH = (const char*)&g_W1h[0][0][0];
        for (int i = tid; i < BCH / 16; i += NT)
            CPA16(smb + OFF_B + i * 16, sH + i * 16);
        CPA_COMMIT();
    }

    // ---- params into smem ----
    for (int i = tid; i < 512; i += NT)
        smf[OFF_B1 / 4 + i] = ((i >> 8) ? b1b : b1a)[i & 255];
    for (int i = tid; i < 2048; i += NT) {
        const int br = i >> 10, rem = i & 1023, n = rem >> 2, q = rem & 3;
        smf[OFF_W2T / 4 + i] = (br ? W2b : W2a)[q * 256 + n];
    }
    if (tid < 8)  smf[OFF_B2 / 4 + tid] = ((tid >> 2) ? b2b : b2a)[tid & 3];
    if (tid < 48) {
        const int br = tid / 24, g = tid % 24;
        float sv, cv;
        sincosf(0.5f * (br ? qwb : qwa)[g], &sv, &cv);
        smf[OFF_TRC / 4 + tid] = cv;  smf[OFF_TRS / 4 + tid] = sv;
    }
    if (tid < 4)
        smf[OFF_PP / 4 + tid] = (tid == 0) ? pwa[0] : (tid == 1) ? pba[0]
                               : (tid == 2) ? pwb[0] : pbb[0];
    for (int i = tid; i < 1024; i += NT) qin[i] = 0.f;

    // ---- x -> fp16 A tile [row][k], stride RS ----
    {
        const int r = tid >> 1, hf = tid & 1;
        const float* srow = state  + (size_t)(rowg0 + r) * 128;
        const float* arow = action + (size_t)(rowg0 + r) * 32;
#pragma unroll 5
        for (int i = 0; i < 20; i++) {
            const int k = hf * 80 + i * 4;
            const float4 v = (k < 128) ? *(const float4*)(srow + k)
                                       : *(const float4*)(arow + (k - 128));
            *(__half2*)(Ah + r * RS + k)     = __floats2half2_rn(v.x, v.y);
            *(__half2*)(Ah + r * RS + k + 2) = __floats2half2_rn(v.z, v.w);
        }
    }
    __syncthreads();

    // ---- ldmatrix byte-address bases ----
    const uint32_t aB0 = smb + OFF_A
        + (uint32_t)((m0 + (lane & 15)) * RS + 8 * (lane >> 4)) * 2;
    const uint32_t aB1 = aB0 + 16u * RS * 2;
    const uint32_t bO0 = (uint32_t)((n0 + 8 * (lane >> 4) + (lane & 7)) * RS
                                    + 8 * ((lane >> 3) & 1)) * 2;
    const uint32_t bO1 = bO0 + 16u * RS * 2;

    // deferred W2 partials: P[0]=mf0 row, P[1]=mf0 row+8, P[2]=mf1 row, P[3]=mf1 row+8
    float P[4][4];
#pragma unroll
    for (int a = 0; a < 4; a++)
#pragma unroll
        for (int j = 0; j < 4; j++) P[a][j] = 0.f;

#pragma unroll 1
    for (int pass = 0; pass < 8; pass++) {
        const int br = pass >> 2, chunk = pass & 3;
        const int nbase = chunk * 64;
        const int buf = pass & 1;

        // prefetch next chunk into other buffer
        if (pass < 7) {
            const int pN = pass + 1;
            const char* sH = (const char*)&g_W1h[pN >> 2][(pN & 3) * 64][0];
            const uint32_t dst = smb + OFF_B + (uint32_t)(pN & 1) * BCH;
            for (int i = tid; i < BCH / 16; i += NT)
                CPA16(dst + i * 16, sH + i * 16);
            CPA_COMMIT();
            CPA_WAIT1();
        } else {
            CPA_WAIT0();
        }
        __syncthreads();

        const uint32_t bB = smb + OFF_B + (uint32_t)buf * BCH;

        float acc[2][4][4];
#pragma unroll
        for (int mf = 0; mf < 2; mf++)
#pragma unroll
            for (int nf = 0; nf < 4; nf++)
#pragma unroll
                for (int c = 0; c < 4; c++) acc[mf][nf][c] = 0.f;

#pragma unroll
        for (int ks = 0; ks < 10; ks++) {
            const uint32_t kb = (uint32_t)(ks * 32);   // 16 elem * 2B
            uint32_t af[2][4], bf[2][4];
            ldsm4(af[0], aB0 + kb);
            ldsm4(af[1], aB1 + kb);
            ldsm4(bf[0], bB + bO0 + kb);
            ldsm4(bf[1], bB + bO1 + kb);
#pragma unroll
            for (int g = 0; g < 2; g++)
#pragma unroll
                for (int h = 0; h < 2; h++)
#pragma unroll
                    for (int mf = 0; mf < 2; mf++)
                        mma_f16(acc[mf][g * 2 + h], af[mf], bf[g][h * 2], bf[g][h * 2 + 1]);
        }

        // ---- bias + relu + W2 contraction into register partials ----
        const float* b1s = smf + OFF_B1 / 4 + br * 256;
        const float* w2t = smf + OFF_W2T / 4 + br * 1024;
#pragma unroll
        for (int mf = 0; mf < 2; mf++)
#pragma unroll
            for (int nf = 0; nf < 4; nf++)
#pragma unroll
                for (int c = 0; c < 2; c++) {
                    const int gcol = nbase + n0 + nf * 8 + 2 * tig + c;
                    const float bb = b1s[gcol];
                    const float4 wv = *(const float4*)(w2t + gcol * 4);
                    const float h0 = fmaxf(acc[mf][nf][c] + bb, 0.f);
                    const float h1 = fmaxf(acc[mf][nf][2 + c] + bb, 0.f);
                    float* pa = P[mf * 2];
                    float* pb2 = P[mf * 2 + 1];
                    pa[0] = fmaf(h0, wv.x, pa[0]);   pa[1] = fmaf(h0, wv.y, pa[1]);
                    pa[2] = fmaf(h0, wv.z, pa[2]);   pa[3] = fmaf(h0, wv.w, pa[3]);
                    pb2[0] = fmaf(h1, wv.x, pb2[0]); pb2[1] = fmaf(h1, wv.y, pb2[1]);
                    pb2[2] = fmaf(h1, wv.z, pb2[2]); pb2[3] = fmaf(h1, wv.w, pb2[3]);
                }

        // flush at branch boundary
        if (chunk == 3) {
#pragma unroll
            for (int off = 1; off <= 2; off <<= 1)
#pragma unroll
                for (int a = 0; a < 4; a++)
#pragma unroll
                    for (int j = 0; j < 4; j++)
                        P[a][j] += __shfl_xor_sync(0xffffffffu, P[a][j], off);
            if (tig == 0) {
                const int rows[4] = {m0 + gid, m0 + gid + 8, m0 + 16 + gid, m0 + 24 + gid};
#pragma unroll
                for (int a = 0; a < 4; a++) {
                    float* qdst = qin + ((br << 7) + rows[a]) * 4;
#pragma unroll
                    for (int j = 0; j < 4; j++) atomicAdd(qdst + j, P[a][j]);
                }
            }
#pragma unroll
            for (int a = 0; a < 4; a++)
#pragma unroll
                for (int j = 0; j < 4; j++) P[a][j] = 0.f;
        }

        __syncthreads();   // all reads of buf done before overwrite
    }
    __syncthreads();

    // ---- quantum circuit: 1 row/thread, 128 rows x 2 branches ----
    {
        const int br = tid >> 7, row = tid & 127;
        const float* b2s = smf + OFF_B2 / 4 + br * 4;
        const float* trc = smf + OFF_TRC / 4 + br * 24;
        const float* trs = smf + OFF_TRS / 4 + br * 24;
        const float pw = smf[OFF_PP / 4 + br * 2];
        const float pb = smf[OFF_PP / 4 + br * 2 + 1];
        const float* qv = qin + ((br << 7) + row) * 4;
        const float th[4] = {qv[0] + b2s[0], qv[1] + b2s[1], qv[2] + b2s[2], qv[3] + b2s[3]};

        float ar[16], ai[16];
#pragma unroll
        for (int i = 0; i < 16; i++) { ar[i] = 0.f; ai[i] = 0.f; }
        ar[0] = 1.f;

        float s0, c0;
        sincosf(0.5f * th[0], &s0, &c0);  g_ry<8>(ar, ai, c0, s0);
        sincosf(0.5f * th[1], &s0, &c0);  g_ry<4>(ar, ai, c0, s0);
        sincosf(0.5f * th[2], &s0, &c0);  g_ry<2>(ar, ai, c0, s0);
        sincosf(0.5f * th[3], &s0, &c0);  g_ry<1>(ar, ai, c0, s0);

#pragma unroll
        for (int l = 0; l < 2; l++) {
            const int lb = l * 12;
            g_rx<8>(ar, ai, trc[lb + 0],  trs[lb + 0]);
            g_ry<8>(ar, ai, trc[lb + 1],  trs[lb + 1]);
            g_rz<8>(ar, ai, trc[lb + 2],  trs[lb + 2]);
            g_rx<4>(ar, ai, trc[lb + 3],  trs[lb + 3]);
            g_ry<4>(ar, ai, trc[lb + 4],  trs[lb + 4]);
            g_rz<4>(ar, ai, trc[lb + 5],  trs[lb + 5]);
            g_rx<2>(ar, ai, trc[lb + 6],  trs[lb + 6]);
            g_ry<2>(ar, ai, trc[lb + 7],  trs[lb + 7]);
            g_rz<2>(ar, ai, trc[lb + 8],  trs[lb + 8]);
            g_rx<1>(ar, ai, trc[lb + 9],  trs[lb + 9]);
            g_ry<1>(ar, ai, trc[lb + 10], trs[lb + 10]);
            g_rz<1>(ar, ai, trc[lb + 11], trs[lb + 11]);
            g_cnot<8, 4>(ar, ai);
            g_cnot<4, 2>(ar, ai);
            g_cnot<2, 1>(ar, ai);
            g_cnot<1, 8>(ar, ai);
        }

        float ev = 0.f;
#pragma unroll
        for (int i = 0; i < 16; i++) {
            const float p = ar[i] * ar[i] + ai[i] * ai[i];
            ev += (i & 8) ? -p : p;
        }
        out[(size_t)br * Btot + rowg0 + row] = fmaf(ev, pw, pb);
    }
}

extern "C" void kernel_launch(void* const* d_in, const int* in_sizes, int n_in,
                              void* d_out, int out_size)
{
    const int Btot = in_sizes[0] / 128;
    static bool attr_set = false;
    if (!attr_set) {
        cudaFuncSetAttribute(qmain, cudaFuncAttributeMaxDynamicSharedMemorySize, SMEM_BYTES);
        attr_set = true;
    }
    qprep<<<80, 256>>>((const float*)d_in[2], (const float*)d_in[6]);
    qmain<<<Btot / TB, NT, SMEM_BYTES>>>(
        (const float*)d_in[0],  (const float*)d_in[1],
        (const float*)d_in[3],  (const float*)d_in[4],  (const float*)d_in[5],
        (const float*)d_in[7],  (const float*)d_in[8],  (const float*)d_in[9],
        (const float*)d_in[10], (const float*)d_in[11],
        (const float*)d_in[12], (const float*)d_in[13],
        (const float*)d_in[14], (const float*)d_in[15],
        (float*)d_out, Btot);
}

// round 9
// speedup vs baseline: 4.5233x; 1.0863x over previous
#include <cuda_runtime.h>
#include <cuda_fp16.h>
#include <math.h>
#include <stdint.h>

#define NT 256
#define TB 128
#define KDIM 160
#define RS 168           // k-stride (elements)

// smem byte offsets
#define OFF_A   0                 // fp16 [128][168] = 43008
#define OFF_B   43008             // [buf][64][168] fp16 : 2 x 21504
#define OFF_QIN 86016             // float [2][128][4]
#define OFF_B1  90112             // float [2][256]
#define OFF_W2F 92160             // uint2 [2][16][32] packed W2 B-frags = 8192
#define OFF_B2  100352
#define OFF_TRC 100384
#define OFF_TRS 100576
#define OFF_PP  100768
#define SMEM_BYTES 100784

#define BCH  21504       // bytes per N=64 chunk (64 x 168 x 2B)

// W1 as fp16, [br][n][RS]
__device__ __align__(16) __half g_W1h[2][256][RS];

__device__ __forceinline__ uint32_t smem_u32(const void* p) {
    uint32_t a;
    asm("{ .reg .u64 t; cvta.to.shared.u64 t, %1; cvt.u32.u64 %0, t; }" : "=r"(a) : "l"(p));
    return a;
}
__device__ __forceinline__ void mma_f16(float (&d)[4], const uint32_t (&a)[4],
                                        uint32_t b0, uint32_t b1) {
    asm volatile(
        "mma.sync.aligned.m16n8k16.row.col.f32.f16.f16.f32 "
        "{%0,%1,%2,%3}, {%4,%5,%6,%7}, {%8,%9}, {%0,%1,%2,%3};"
        : "+f"(d[0]), "+f"(d[1]), "+f"(d[2]), "+f"(d[3])
        : "r"(a[0]), "r"(a[1]), "r"(a[2]), "r"(a[3]), "r"(b0), "r"(b1));
}
__device__ __forceinline__ void mma_f16u(float (&d)[4], uint32_t a0, uint32_t a1,
                                         uint32_t a2, uint32_t a3,
                                         uint32_t b0, uint32_t b1) {
    asm volatile(
        "mma.sync.aligned.m16n8k16.row.col.f32.f16.f16.f32 "
        "{%0,%1,%2,%3}, {%4,%5,%6,%7}, {%8,%9}, {%0,%1,%2,%3};"
        : "+f"(d[0]), "+f"(d[1]), "+f"(d[2]), "+f"(d[3])
        : "r"(a0), "r"(a1), "r"(a2), "r"(a3), "r"(b0), "r"(b1));
}
__device__ __forceinline__ void ldsm4(uint32_t (&r)[4], uint32_t addr) {
    asm volatile("ldmatrix.sync.aligned.m8n8.x4.shared.b16 {%0,%1,%2,%3}, [%4];"
        : "=r"(r[0]), "=r"(r[1]), "=r"(r[2]), "=r"(r[3]) : "r"(addr));
}
__device__ __forceinline__ uint32_t h2u(float a, float b) {
    __half2 h = __floats2half2_rn(a, b);
    return *(uint32_t*)&h;
}
#define CPA16(dst, src) asm volatile("cp.async.cg.shared.global [%0], [%1], 16;" :: "r"(dst), "l"(src))
#define CPA_COMMIT()    asm volatile("cp.async.commit_group;")
#define CPA_WAIT1()     asm volatile("cp.async.wait_group 1;")
#define CPA_WAIT0()     asm volatile("cp.async.wait_group 0;")

// ---------------- quantum gates on 16-amplitude register state ----------------
template<int M>
__device__ __forceinline__ void g_ry(float (&ar)[16], float (&ai)[16], float c, float s) {
#pragma unroll
    for (int i = 0; i < 16; i++) if (!(i & M)) {
        const int j = i | M;
        float xr = ar[i], xi = ai[i], yr = ar[j], yi = ai[j];
        ar[i] = c * xr - s * yr;  ai[i] = c * xi - s * yi;
        ar[j] = s * xr + c * yr;  ai[j] = s * xi + c * yi;
    }
}
template<int M>
__device__ __forceinline__ void g_rx(float (&ar)[16], float (&ai)[16], float c, float s) {
#pragma unroll
    for (int i = 0; i < 16; i++) if (!(i & M)) {
        const int j = i | M;
        float xr = ar[i], xi = ai[i], yr = ar[j], yi = ai[j];
        ar[i] = c * xr + s * yi;   ai[i] = c * xi - s * yr;
        ar[j] = s * xi + c * yr;   ai[j] = -s * xr + c * yi;
    }
}
template<int M>
__device__ __forceinline__ void g_rz(float (&ar)[16], float (&ai)[16], float c, float s) {
#pragma unroll
    for (int i = 0; i < 16; i++) if (!(i & M)) {
        const int j = i | M;
        float xr = ar[i], xi = ai[i], yr = ar[j], yi = ai[j];
        ar[i] = c * xr + s * xi;   ai[i] = c * xi - s * xr;
        ar[j] = c * yr - s * yi;   ai[j] = c * yi + s * yr;
    }
}
template<int MC, int MT>
__device__ __forceinline__ void g_cnot(float (&ar)[16], float (&ai)[16]) {
#pragma unroll
    for (int i = 0; i < 16; i++) if ((i & MC) && !(i & MT)) {
        const int j = i | MT;
        float tr = ar[i]; ar[i] = ar[j]; ar[j] = tr;
        float ti = ai[i]; ai[i] = ai[j]; ai[j] = ti;
    }
}

// ---------------- prep: W1 -> fp16 ----------------
__global__ void qprep(const float* __restrict__ W1a, const float* __restrict__ W1b) {
    const int t = blockIdx.x * 256 + threadIdx.x;    // 0..20479
    const int br = t / 10240;
    const int rem = t % 10240;
    const int n = rem / 40, k4 = rem % 40;
    const float4 v = *(const float4*)((br ? W1b : W1a) + (size_t)n * KDIM + k4 * 4);
    __half2* dst = (__half2*)&g_W1h[br][n][k4 * 4];
    dst[0] = __floats2half2_rn(v.x, v.y);
    dst[1] = __floats2half2_rn(v.z, v.w);
}

// ---------------- main kernel ----------------
__global__ __launch_bounds__(NT, 2)
void qmain(const float* __restrict__ state, const float* __restrict__ action,
           const float* __restrict__ b1a, const float* __restrict__ W2a, const float* __restrict__ b2a,
           const float* __restrict__ b1b, const float* __restrict__ W2b, const float* __restrict__ b2b,
           const float* __restrict__ qwa, const float* __restrict__ qwb,
           const float* __restrict__ pwa, const float* __restrict__ pba,
           const float* __restrict__ pwb, const float* __restrict__ pbb,
           float* __restrict__ out, int Btot)
{
    extern __shared__ __align__(16) unsigned char smp[];
    float* smf = (float*)smp;
    __half* Ah = (__half*)(smp + OFF_A);
    float* qin = smf + OFF_QIN / 4;
    const uint32_t smb = smem_u32(smp);

    const int tid = threadIdx.x;
    const int lane = tid & 31, w = tid >> 5;
    const int gid = lane >> 2, tig = lane & 3;
    const int wm = w & 3, wn = w >> 2;
    const int m0 = wm * 32, n0 = wn * 32;
    const int rowg0 = blockIdx.x * TB;

    // ---- kick off B load for pass 0 (buf 0) ----
    {
        const char* sH = (const char*)&g_W1h[0][0][0];
        for (int i = tid; i < BCH / 16; i += NT)
            CPA16(smb + OFF_B + i * 16, sH + i * 16);
        CPA_COMMIT();
    }

    // ---- params into smem ----
    for (int i = tid; i < 512; i += NT)
        smf[OFF_B1 / 4 + i] = ((i >> 8) ? b1b : b1a)[i & 255];
    // W2 packed as per-lane B-fragments: [br][group(16 cols)][lane] -> 2 u32
    for (int i = tid; i < 1024; i += NT) {
        const int br = i >> 9, g = (i >> 5) & 15, ln = i & 31;
        const int gq = ln >> 2, gt = ln & 3;
        const int kc = g * 16 + 2 * gt;
        const float* W2 = br ? W2b : W2a;
        uint32_t r0 = 0, r1 = 0;
        if (gq < 4) {
            r0 = h2u(W2[gq * 256 + kc],     W2[gq * 256 + kc + 1]);
            r1 = h2u(W2[gq * 256 + kc + 8], W2[gq * 256 + kc + 9]);
        }
        ((uint2*)(smp + OFF_W2F))[i] = make_uint2(r0, r1);
    }
    if (tid < 8)  smf[OFF_B2 / 4 + tid] = ((tid >> 2) ? b2b : b2a)[tid & 3];
    if (tid < 48) {
        const int br = tid / 24, g = tid % 24;
        float sv, cv;
        sincosf(0.5f * (br ? qwb : qwa)[g], &sv, &cv);
        smf[OFF_TRC / 4 + tid] = cv;  smf[OFF_TRS / 4 + tid] = sv;
    }
    if (tid < 4)
        smf[OFF_PP / 4 + tid] = (tid == 0) ? pwa[0] : (tid == 1) ? pba[0]
                               : (tid == 2) ? pwb[0] : pbb[0];
    for (int i = tid; i < 1024; i += NT) qin[i] = 0.f;

    // ---- x -> fp16 A tile [row][k], stride RS ----
    {
        const int r = tid >> 1, hf = tid & 1;
        const float* srow = state  + (size_t)(rowg0 + r) * 128;
        const float* arow = action + (size_t)(rowg0 + r) * 32;
#pragma unroll 5
        for (int i = 0; i < 20; i++) {
            const int k = hf * 80 + i * 4;
            const float4 v = (k < 128) ? *(const float4*)(srow + k)
                                       : *(const float4*)(arow + (k - 128));
            *(__half2*)(Ah + r * RS + k)     = __floats2half2_rn(v.x, v.y);
            *(__half2*)(Ah + r * RS + k + 2) = __floats2half2_rn(v.z, v.w);
        }
    }
    __syncthreads();

    // ---- ldmatrix byte-address bases ----
    const uint32_t aB0 = smb + OFF_A
        + (uint32_t)((m0 + (lane & 15)) * RS + 8 * (lane >> 4)) * 2;
    const uint32_t aB1 = aB0 + 16u * RS * 2;
    const uint32_t bO0 = (uint32_t)((n0 + 8 * (lane >> 4) + (lane & 7)) * RS
                                    + 8 * ((lane >> 3) & 1)) * 2;
    const uint32_t bO1 = bO0 + 16u * RS * 2;

    // q partial accumulators (tensor-core epilogue), per mf fragment
    float qacc[2][4];
#pragma unroll
    for (int mf = 0; mf < 2; mf++)
#pragma unroll
        for (int c = 0; c < 4; c++) qacc[mf][c] = 0.f;

#pragma unroll 1
    for (int pass = 0; pass < 8; pass++) {
        const int br = pass >> 2, chunk = pass & 3;
        const int nbase = chunk * 64;
        const int buf = pass & 1;

        // prefetch next chunk into other buffer
        if (pass < 7) {
            const int pN = pass + 1;
            const char* sH = (const char*)&g_W1h[pN >> 2][(pN & 3) * 64][0];
            const uint32_t dst = smb + OFF_B + (uint32_t)(pN & 1) * BCH;
            for (int i = tid; i < BCH / 16; i += NT)
                CPA16(dst + i * 16, sH + i * 16);
            CPA_COMMIT();
            CPA_WAIT1();
        } else {
            CPA_WAIT0();
        }
        __syncthreads();

        const uint32_t bB = smb + OFF_B + (uint32_t)buf * BCH;

        float acc[2][4][4];
#pragma unroll
        for (int mf = 0; mf < 2; mf++)
#pragma unroll
            for (int nf = 0; nf < 4; nf++)
#pragma unroll
                for (int c = 0; c < 4; c++) acc[mf][nf][c] = 0.f;

#pragma unroll
        for (int ks = 0; ks < 10; ks++) {
            const uint32_t kb = (uint32_t)(ks * 32);   // 16 elem * 2B
            uint32_t af[2][4], bf[2][4];
            ldsm4(af[0], aB0 + kb);
            ldsm4(af[1], aB1 + kb);
            ldsm4(bf[0], bB + bO0 + kb);
            ldsm4(bf[1], bB + bO1 + kb);
#pragma unroll
            for (int g = 0; g < 2; g++)
#pragma unroll
                for (int h = 0; h < 2; h++)
#pragma unroll
                    for (int mf = 0; mf < 2; mf++)
                        mma_f16(acc[mf][g * 2 + h], af[mf], bf[g][h * 2], bf[g][h * 2 + 1]);
        }

        // ---- tensor-core epilogue: bias+relu -> fp16 frags -> MMA vs W2 frags ----
        {
            const float2* b1v = (const float2*)(smf + OFF_B1 / 4 + br * 256);
            const uint2* w2f = (const uint2*)(smp + OFF_W2F);
            const int gbase = (nbase + n0) >> 4;
            const uint2 bfA = w2f[(((br << 4) + gbase) << 5) + lane];
            const uint2 bfB = w2f[(((br << 4) + gbase + 1) << 5) + lane];
#pragma unroll
            for (int ks = 0; ks < 2; ks++) {
                const int nfa = ks * 2, nfb = nfa + 1;
                const float2 bba = b1v[((nbase + n0 + nfa * 8) >> 1) + tig];
                const float2 bbb = b1v[((nbase + n0 + nfb * 8) >> 1) + tig];
                const uint2 bfr = ks ? bfB : bfA;
#pragma unroll
                for (int mf = 0; mf < 2; mf++) {
                    const uint32_t a0 = h2u(fmaxf(acc[mf][nfa][0] + bba.x, 0.f),
                                            fmaxf(acc[mf][nfa][1] + bba.y, 0.f));
                    const uint32_t a1 = h2u(fmaxf(acc[mf][nfa][2] + bba.x, 0.f),
                                            fmaxf(acc[mf][nfa][3] + bba.y, 0.f));
                    const uint32_t a2 = h2u(fmaxf(acc[mf][nfb][0] + bbb.x, 0.f),
                                            fmaxf(acc[mf][nfb][1] + bbb.y, 0.f));
                    const uint32_t a3 = h2u(fmaxf(acc[mf][nfb][2] + bbb.x, 0.f),
                                            fmaxf(acc[mf][nfb][3] + bbb.y, 0.f));
                    mma_f16u(qacc[mf], a0, a1, a2, a3, bfr.x, bfr.y);
                }
            }
        }

        // flush q partials at branch boundary
        if (chunk == 3) {
            if (tig < 2) {
                const int qb = 2 * tig;
#pragma unroll
                for (int mf = 0; mf < 2; mf++) {
                    float* q0 = qin + ((br << 7) + m0 + mf * 16 + gid) * 4 + qb;
                    float* q1 = qin + ((br << 7) + m0 + mf * 16 + gid + 8) * 4 + qb;
                    atomicAdd(q0,     qacc[mf][0]);
                    atomicAdd(q0 + 1, qacc[mf][1]);
                    atomicAdd(q1,     qacc[mf][2]);
                    atomicAdd(q1 + 1, qacc[mf][3]);
                }
            }
#pragma unroll
            for (int mf = 0; mf < 2; mf++)
#pragma unroll
                for (int c = 0; c < 4; c++) qacc[mf][c] = 0.f;
        }

        __syncthreads();   // all reads of buf done before overwrite
    }
    __syncthreads();

    // ---- quantum circuit: 1 row/thread, 128 rows x 2 branches ----
    {
        const int br = tid >> 7, row = tid & 127;
        const float* b2s = smf + OFF_B2 / 4 + br * 4;
        const float* trc = smf + OFF_TRC / 4 + br * 24;
        const float* trs = smf + OFF_TRS / 4 + br * 24;
        const float pw = smf[OFF_PP / 4 + br * 2];
        const float pb = smf[OFF_PP / 4 + br * 2 + 1];
        const float* qv = qin + ((br << 7) + row) * 4;
        const float th[4] = {qv[0] + b2s[0], qv[1] + b2s[1], qv[2] + b2s[2], qv[3] + b2s[3]};

        float ar[16], ai[16];
#pragma unroll
        for (int i = 0; i < 16; i++) { ar[i] = 0.f; ai[i] = 0.f; }
        ar[0] = 1.f;

        float s0, c0;
        sincosf(0.5f * th[0], &s0, &c0);  g_ry<8>(ar, ai, c0, s0);
        sincosf(0.5f * th[1], &s0, &c0);  g_ry<4>(ar, ai, c0, s0);
        sincosf(0.5f * th[2], &s0, &c0);  g_ry<2>(ar, ai, c0, s0);
        sincosf(0.5f * th[3], &s0, &c0);  g_ry<1>(ar, ai, c0, s0);

#pragma unroll
        for (int l = 0; l < 2; l++) {
            const int lb = l * 12;
            g_rx<8>(ar, ai, trc[lb + 0],  trs[lb + 0]);
            g_ry<8>(ar, ai, trc[lb + 1],  trs[lb + 1]);
            g_rz<8>(ar, ai, trc[lb + 2],  trs[lb + 2]);
            g_rx<4>(ar, ai, trc[lb + 3],  trs[lb + 3]);
            g_ry<4>(ar, ai, trc[lb + 4],  trs[lb + 4]);
            g_rz<4>(ar, ai, trc[lb + 5],  trs[lb + 5]);
            g_rx<2>(ar, ai, trc[lb + 6],  trs[lb + 6]);
            g_ry<2>(ar, ai, trc[lb + 7],  trs[lb + 7]);
            g_rz<2>(ar, ai, trc[lb + 8],  trs[lb + 8]);
            g_rx<1>(ar, ai, trc[lb + 9],  trs[lb + 9]);
            g_ry<1>(ar, ai, trc[lb + 10], trs[lb + 10]);
            g_rz<1>(ar, ai, trc[lb + 11], trs[lb + 11]);
            g_cnot<8, 4>(ar, ai);
            g_cnot<4, 2>(ar, ai);
            g_cnot<2, 1>(ar, ai);
            g_cnot<1, 8>(ar, ai);
        }

        float ev = 0.f;
#pragma unroll
        for (int i = 0; i < 16; i++) {
            const float p = ar[i] * ar[i] + ai[i] * ai[i];
            ev += (i & 8) ? -p : p;
        }
        out[(size_t)br * Btot + rowg0 + row] = fmaf(ev, pw, pb);
    }
}

extern "C" void kernel_launch(void* const* d_in, const int* in_sizes, int n_in,
                              void* d_out, int out_size)
{
    const int Btot = in_sizes[0] / 128;
    static bool attr_set = false;
    if (!attr_set) {
        cudaFuncSetAttribute(qmain, cudaFuncAttributeMaxDynamicSharedMemorySize, SMEM_BYTES);
        attr_set = true;
    }
    qprep<<<80, 256>>>((const float*)d_in[2], (const float*)d_in[6]);
    qmain<<<Btot / TB, NT, SMEM_BYTES>>>(
        (const float*)d_in[0],  (const float*)d_in[1],
        (const float*)d_in[3],  (const float*)d_in[4],  (const float*)d_in[5],
        (const float*)d_in[7],  (const float*)d_in[8],  (const float*)d_in[9],
        (const float*)d_in[10], (const float*)d_in[11],
        (const float*)d_in[12], (const float*)d_in[13],
        (const float*)d_in[14], (const float*)d_in[15],
        (float*)d_out, Btot);
}

// round 10
// speedup vs baseline: 4.6389x; 1.0256x over previous
#include <cuda_runtime.h>
#include <cuda_fp16.h>
#include <math.h>
#include <stdint.h>

#define NT 256
#define TB 128
#define KDIM 160
#define RS 168           // k-stride (elements)

// smem byte offsets
#define OFF_A   0                 // fp16 [128][168] = 43008
#define OFF_B   43008             // [buf][64][168] fp16 : 2 x 21504
#define OFF_QIN 86016             // float [2][128][4]
#define OFF_B1  90112             // float [2][256]
#define OFF_W2F 92160             // uint2 [2][16][32] packed W2 B-frags = 8192
#define OFF_B2  100352            // float [2][4]
#define OFF_A16 100384            // float [2][16][16] quadratic-form matrices
#define OFF_PP  102432
#define SMEM_BYTES 102448

#define BCH  21504       // bytes per N=64 chunk (64 x 168 x 2B)

// W1 as fp16, [br][n][RS]
__device__ __align__(16) __half g_W1h[2][256][RS];
// quadratic-form matrices A = Re(U^T Z0 U), [br][i][j]
__device__ float g_A[2][16][16];

__device__ __forceinline__ uint32_t smem_u32(const void* p) {
    uint32_t a;
    asm("{ .reg .u64 t; cvta.to.shared.u64 t, %1; cvt.u32.u64 %0, t; }" : "=r"(a) : "l"(p));
    return a;
}
__device__ __forceinline__ void mma_f16(float (&d)[4], const uint32_t (&a)[4],
                                        uint32_t b0, uint32_t b1) {
    asm volatile(
        "mma.sync.aligned.m16n8k16.row.col.f32.f16.f16.f32 "
        "{%0,%1,%2,%3}, {%4,%5,%6,%7}, {%8,%9}, {%0,%1,%2,%3};"
        : "+f"(d[0]), "+f"(d[1]), "+f"(d[2]), "+f"(d[3])
        : "r"(a[0]), "r"(a[1]), "r"(a[2]), "r"(a[3]), "r"(b0), "r"(b1));
}
__device__ __forceinline__ void mma_f16u(float (&d)[4], uint32_t a0, uint32_t a1,
                                         uint32_t a2, uint32_t a3,
                                         uint32_t b0, uint32_t b1) {
    asm volatile(
        "mma.sync.aligned.m16n8k16.row.col.f32.f16.f16.f32 "
        "{%0,%1,%2,%3}, {%4,%5,%6,%7}, {%8,%9}, {%0,%1,%2,%3};"
        : "+f"(d[0]), "+f"(d[1]), "+f"(d[2]), "+f"(d[3])
        : "r"(a0), "r"(a1), "r"(a2), "r"(a3), "r"(b0), "r"(b1));
}
__device__ __forceinline__ void ldsm4(uint32_t (&r)[4], uint32_t addr) {
    asm volatile("ldmatrix.sync.aligned.m8n8.x4.shared.b16 {%0,%1,%2,%3}, [%4];"
        : "=r"(r[0]), "=r"(r[1]), "=r"(r[2]), "=r"(r[3]) : "r"(addr));
}
__device__ __forceinline__ uint32_t h2u(float a, float b) {
    __half2 h = __floats2half2_rn(a, b);
    return *(uint32_t*)&h;
}
#define CPA16(dst, src) asm volatile("cp.async.cg.shared.global [%0], [%1], 16;" :: "r"(dst), "l"(src))
#define CPA_COMMIT()    asm volatile("cp.async.commit_group;")
#define CPA_WAIT1()     asm volatile("cp.async.wait_group 1;")
#define CPA_WAIT0()     asm volatile("cp.async.wait_group 0;")

// ---------------- quantum gates on 16-amplitude register state ----------------
template<int M>
__device__ __forceinline__ void g_ry(float (&ar)[16], float (&ai)[16], float c, float s) {
#pragma unroll
    for (int i = 0; i < 16; i++) if (!(i & M)) {
        const int j = i | M;
        float xr = ar[i], xi = ai[i], yr = ar[j], yi = ai[j];
        ar[i] = c * xr - s * yr;  ai[i] = c * xi - s * yi;
        ar[j] = s * xr + c * yr;  ai[j] = s * xi + c * yi;
    }
}
template<int M>
__device__ __forceinline__ void g_rx(float (&ar)[16], float (&ai)[16], float c, float s) {
#pragma unroll
    for (int i = 0; i < 16; i++) if (!(i & M)) {
        const int j = i | M;
        float xr = ar[i], xi = ai[i], yr = ar[j], yi = ai[j];
        ar[i] = c * xr + s * yi;   ai[i] = c * xi - s * yr;
        ar[j] = s * xi + c * yr;   ai[j] = -s * xr + c * yi;
    }
}
template<int M>
__device__ __forceinline__ void g_rz(float (&ar)[16], float (&ai)[16], float c, float s) {
#pragma unroll
    for (int i = 0; i < 16; i++) if (!(i & M)) {
        const int j = i | M;
        float xr = ar[i], xi = ai[i], yr = ar[j], yi = ai[j];
        ar[i] = c * xr + s * xi;   ai[i] = c * xi - s * xr;
        ar[j] = c * yr - s * yi;   ai[j] = c * yi + s * yr;
    }
}
template<int MC, int MT>
__device__ __forceinline__ void g_cnot(float (&ar)[16], float (&ai)[16]) {
#pragma unroll
    for (int i = 0; i < 16; i++) if ((i & MC) && !(i & MT)) {
        const int j = i | MT;
        float tr = ar[i]; ar[i] = ar[j]; ar[j] = tr;
        float ti = ai[i]; ai[i] = ai[j]; ai[j] = ti;
    }
}

// ---------------- prep 1: W1 -> fp16 ----------------
__global__ void qprep(const float* __restrict__ W1a, const float* __restrict__ W1b) {
    const int t = blockIdx.x * 256 + threadIdx.x;    // 0..20479
    const int br = t / 10240;
    const int rem = t % 10240;
    const int n = rem / 40, k4 = rem % 40;
    const float4 v = *(const float4*)((br ? W1b : W1a) + (size_t)n * KDIM + k4 * 4);
    __half2* dst = (__half2*)&g_W1h[br][n][k4 * 4];
    dst[0] = __floats2half2_rn(v.x, v.y);
    dst[1] = __floats2half2_rn(v.z, v.w);
}

// ---------------- prep 2: fixed-circuit unitary -> quadratic form A ----------------
__global__ void qcirc(const float* __restrict__ qwa, const float* __restrict__ qwb) {
    __shared__ float Ur[2][16][16], Ui[2][16][16];   // [br][k][col]
    const int tid = threadIdx.x;   // 512 threads
    if (tid < 32) {
        const int br = tid >> 4, col = tid & 15;
        const float* qw = br ? qwb : qwa;
        float trc[24], trs[24];
#pragma unroll
        for (int g = 0; g < 24; g++) sincosf(0.5f * qw[g], &trs[g], &trc[g]);
        float ar[16], ai[16];
#pragma unroll
        for (int i = 0; i < 16; i++) { ar[i] = (i == col) ? 1.f : 0.f; ai[i] = 0.f; }
#pragma unroll
        for (int l = 0; l < 2; l++) {
            const int lb = l * 12;
            g_rx<8>(ar, ai, trc[lb + 0],  trs[lb + 0]);
            g_ry<8>(ar, ai, trc[lb + 1],  trs[lb + 1]);
            g_rz<8>(ar, ai, trc[lb + 2],  trs[lb + 2]);
            g_rx<4>(ar, ai, trc[lb + 3],  trs[lb + 3]);
            g_ry<4>(ar, ai, trc[lb + 4],  trs[lb + 4]);
            g_rz<4>(ar, ai, trc[lb + 5],  trs[lb + 5]);
            g_rx<2>(ar, ai, trc[lb + 6],  trs[lb + 6]);
            g_ry<2>(ar, ai, trc[lb + 7],  trs[lb + 7]);
            g_rz<2>(ar, ai, trc[lb + 8],  trs[lb + 8]);
            g_rx<1>(ar, ai, trc[lb + 9],  trs[lb + 9]);
            g_ry<1>(ar, ai, trc[lb + 10], trs[lb + 10]);
            g_rz<1>(ar, ai, trc[lb + 11], trs[lb + 11]);
            g_cnot<8, 4>(ar, ai);
            g_cnot<4, 2>(ar, ai);
            g_cnot<2, 1>(ar, ai);
            g_cnot<1, 8>(ar, ai);
        }
#pragma unroll
        for (int k = 0; k < 16; k++) { Ur[br][k][col] = ar[k]; Ui[br][k][col] = ai[k]; }
    }
    __syncthreads();
    {
        const int br = tid >> 8, idx = tid & 255;
        const int i = idx >> 4, j = idx & 15;
        float s = 0.f;
#pragma unroll
        for (int k = 0; k < 16; k++) {
            const float z = (k & 8) ? -1.f : 1.f;
            s += z * (Ur[br][k][i] * Ur[br][k][j] + Ui[br][k][i] * Ui[br][k][j]);
        }
        g_A[br][i][j] = s;
    }
}

// ---------------- main kernel ----------------
__global__ __launch_bounds__(NT, 2)
void qmain(const float* __restrict__ state, const float* __restrict__ action,
           const float* __restrict__ b1a, const float* __restrict__ W2a, const float* __restrict__ b2a,
           const float* __restrict__ b1b, const float* __restrict__ W2b, const float* __restrict__ b2b,
           const float* __restrict__ pwa, const float* __restrict__ pba,
           const float* __restrict__ pwb, const float* __restrict__ pbb,
           float* __restrict__ out, int Btot)
{
    extern __shared__ __align__(16) unsigned char smp[];
    float* smf = (float*)smp;
    __half* Ah = (__half*)(smp + OFF_A);
    float* qin = smf + OFF_QIN / 4;
    const uint32_t smb = smem_u32(smp);

    const int tid = threadIdx.x;
    const int lane = tid & 31, w = tid >> 5;
    const int gid = lane >> 2, tig = lane & 3;
    const int wm = w & 3, wn = w >> 2;
    const int m0 = wm * 32, n0 = wn * 32;
    const int rowg0 = blockIdx.x * TB;

    // ---- kick off B load for pass 0 (buf 0) ----
    {
        const char* sH = (const char*)&g_W1h[0][0][0];
        for (int i = tid; i < BCH / 16; i += NT)
            CPA16(smb + OFF_B + i * 16, sH + i * 16);
        CPA_COMMIT();
    }

    // ---- params into smem ----
    for (int i = tid; i < 512; i += NT)
        smf[OFF_B1 / 4 + i] = ((i >> 8) ? b1b : b1a)[i & 255];
    // W2 packed as per-lane B-fragments: [br][group(16 cols)][lane] -> 2 u32
    for (int i = tid; i < 1024; i += NT) {
        const int br = i >> 9, g = (i >> 5) & 15, ln = i & 31;
        const int gq = ln >> 2, gt = ln & 3;
        const int kc = g * 16 + 2 * gt;
        const float* W2 = br ? W2b : W2a;
        uint32_t r0 = 0, r1 = 0;
        if (gq < 4) {
            r0 = h2u(W2[gq * 256 + kc],     W2[gq * 256 + kc + 1]);
            r1 = h2u(W2[gq * 256 + kc + 8], W2[gq * 256 + kc + 9]);
        }
        ((uint2*)(smp + OFF_W2F))[i] = make_uint2(r0, r1);
    }
    if (tid < 8)  smf[OFF_B2 / 4 + tid] = ((tid >> 2) ? b2b : b2a)[tid & 3];
    for (int i = tid; i < 512; i += NT)
        smf[OFF_A16 / 4 + i] = ((const float*)g_A)[i];
    if (tid < 4)
        smf[OFF_PP / 4 + tid] = (tid == 0) ? pwa[0] : (tid == 1) ? pba[0]
                               : (tid == 2) ? pwb[0] : pbb[0];
    for (int i = tid; i < 1024; i += NT) qin[i] = 0.f;

    // ---- x -> fp16 A tile [row][k], stride RS ----
    {
        const int r = tid >> 1, hf = tid & 1;
        const float* srow = state  + (size_t)(rowg0 + r) * 128;
        const float* arow = action + (size_t)(rowg0 + r) * 32;
#pragma unroll 5
        for (int i = 0; i < 20; i++) {
            const int k = hf * 80 + i * 4;
            const float4 v = (k < 128) ? *(const float4*)(srow + k)
                                       : *(const float4*)(arow + (k - 128));
            *(__half2*)(Ah + r * RS + k)     = __floats2half2_rn(v.x, v.y);
            *(__half2*)(Ah + r * RS + k + 2) = __floats2half2_rn(v.z, v.w);
        }
    }
    __syncthreads();

    // ---- ldmatrix byte-address bases ----
    const uint32_t aB0 = smb + OFF_A
        + (uint32_t)((m0 + (lane & 15)) * RS + 8 * (lane >> 4)) * 2;
    const uint32_t aB1 = aB0 + 16u * RS * 2;
    const uint32_t bO0 = (uint32_t)((n0 + 8 * (lane >> 4) + (lane & 7)) * RS
                                    + 8 * ((lane >> 3) & 1)) * 2;
    const uint32_t bO1 = bO0 + 16u * RS * 2;

    // q partial accumulators (tensor-core epilogue), per mf fragment
    float qacc[2][4];
#pragma unroll
    for (int mf = 0; mf < 2; mf++)
#pragma unroll
        for (int c = 0; c < 4; c++) qacc[mf][c] = 0.f;

#pragma unroll 1
    for (int pass = 0; pass < 8; pass++) {
        const int br = pass >> 2, chunk = pass & 3;
        const int nbase = chunk * 64;
        const int buf = pass & 1;

        // prefetch next chunk into other buffer
        if (pass < 7) {
            const int pN = pass + 1;
            const char* sH = (const char*)&g_W1h[pN >> 2][(pN & 3) * 64][0];
            const uint32_t dst = smb + OFF_B + (uint32_t)(pN & 1) * BCH;
            for (int i = tid; i < BCH / 16; i += NT)
                CPA16(dst + i * 16, sH + i * 16);
            CPA_COMMIT();
            CPA_WAIT1();
        } else {
            CPA_WAIT0();
        }
        __syncthreads();

        const uint32_t bB = smb + OFF_B + (uint32_t)buf * BCH;

        float acc[2][4][4];
#pragma unroll
        for (int mf = 0; mf < 2; mf++)
#pragma unroll
            for (int nf = 0; nf < 4; nf++)
#pragma unroll
                for (int c = 0; c < 4; c++) acc[mf][nf][c] = 0.f;

#pragma unroll
        for (int ks = 0; ks < 10; ks++) {
            const uint32_t kb = (uint32_t)(ks * 32);   // 16 elem * 2B
            uint32_t af[2][4], bf[2][4];
            ldsm4(af[0], aB0 + kb);
            ldsm4(af[1], aB1 + kb);
            ldsm4(bf[0], bB + bO0 + kb);
            ldsm4(bf[1], bB + bO1 + kb);
#pragma unroll
            for (int g = 0; g < 2; g++)
#pragma unroll
                for (int h = 0; h < 2; h++)
#pragma unroll
                    for (int mf = 0; mf < 2; mf++)
                        mma_f16(acc[mf][g * 2 + h], af[mf], bf[g][h * 2], bf[g][h * 2 + 1]);
        }

        // ---- tensor-core epilogue: bias+relu -> fp16 frags -> MMA vs W2 frags ----
        {
            const float2* b1v = (const float2*)(smf + OFF_B1 / 4 + br * 256);
            const uint2* w2f = (const uint2*)(smp + OFF_W2F);
            const int gbase = (nbase + n0) >> 4;
            const uint2 bfA = w2f[(((br << 4) + gbase) << 5) + lane];
            const uint2 bfB = w2f[(((br << 4) + gbase + 1) << 5) + lane];
#pragma unroll
            for (int ks = 0; ks < 2; ks++) {
                const int nfa = ks * 2, nfb = nfa + 1;
                const float2 bba = b1v[((nbase + n0 + nfa * 8) >> 1) + tig];
                const float2 bbb = b1v[((nbase + n0 + nfb * 8) >> 1) + tig];
                const uint2 bfr = ks ? bfB : bfA;
#pragma unroll
                for (int mf = 0; mf < 2; mf++) {
                    const uint32_t a0 = h2u(fmaxf(acc[mf][nfa][0] + bba.x, 0.f),
                                            fmaxf(acc[mf][nfa][1] + bba.y, 0.f));
                    const uint32_t a1 = h2u(fmaxf(acc[mf][nfa][2] + bba.x, 0.f),
                                            fmaxf(acc[mf][nfa][3] + bba.y, 0.f));
                    const uint32_t a2 = h2u(fmaxf(acc[mf][nfb][0] + bbb.x, 0.f),
                                            fmaxf(acc[mf][nfb][1] + bbb.y, 0.f));
                    const uint32_t a3 = h2u(fmaxf(acc[mf][nfb][2] + bbb.x, 0.f),
                                            fmaxf(acc[mf][nfb][3] + bbb.y, 0.f));
                    mma_f16u(qacc[mf], a0, a1, a2, a3, bfr.x, bfr.y);
                }
            }
        }

        // flush q partials at branch boundary
        if (chunk == 3) {
            if (tig < 2) {
                const int qb = 2 * tig;
#pragma unroll
                for (int mf = 0; mf < 2; mf++) {
                    float* q0 = qin + ((br << 7) + m0 + mf * 16 + gid) * 4 + qb;
                    float* q1 = qin + ((br << 7) + m0 + mf * 16 + gid + 8) * 4 + qb;
                    atomicAdd(q0,     qacc[mf][0]);
                    atomicAdd(q0 + 1, qacc[mf][1]);
                    atomicAdd(q1,     qacc[mf][2]);
                    atomicAdd(q1 + 1, qacc[mf][3]);
                }
            }
#pragma unroll
            for (int mf = 0; mf < 2; mf++)
#pragma unroll
                for (int c = 0; c < 4; c++) qacc[mf][c] = 0.f;
        }

        __syncthreads();   // all reads of buf done before overwrite
    }
    __syncthreads();

    // ---- quadratic-form epilogue: 1 row/thread, 128 rows x 2 branches ----
    {
        const int br = tid >> 7, row = tid & 127;
        const float* b2s = smf + OFF_B2 / 4 + br * 4;
        const float* Ab = smf + OFF_A16 / 4 + br * 256;
        const float pw = smf[OFF_PP / 4 + br * 2];
        const float pb = smf[OFF_PP / 4 + br * 2 + 1];
        const float* qv = qin + ((br << 7) + row) * 4;

        float c[4], s[4];
#pragma unroll
        for (int q = 0; q < 4; q++)
            sincosf(0.5f * (qv[q] + b2s[q]), &s[q], &c[q]);

        // v[i]: bit3=qubit0 ... bit0=qubit3
        float p01[4] = {c[0] * c[1], c[0] * s[1], s[0] * c[1], s[0] * s[1]};
        float p23[4] = {c[2] * c[3], c[2] * s[3], s[2] * c[3], s[2] * s[3]};
        float v[16];
#pragma unroll
        for (int hi = 0; hi < 4; hi++)
#pragma unroll
            for (int lo = 0; lo < 4; lo++)
                v[hi * 4 + lo] = p01[hi] * p23[lo];

        float ev = 0.f;
#pragma unroll
        for (int i = 0; i < 16; i++) {
            const float4* Ar = (const float4*)(Ab + i * 16);
            float wi = 0.f;
#pragma unroll
            for (int j4 = 0; j4 < 4; j4++) {
                const float4 a4 = Ar[j4];
                wi = fmaf(a4.x, v[j4 * 4 + 0], wi);
                wi = fmaf(a4.y, v[j4 * 4 + 1], wi);
                wi = fmaf(a4.z, v[j4 * 4 + 2], wi);
                wi = fmaf(a4.w, v[j4 * 4 + 3], wi);
            }
            ev = fmaf(v[i], wi, ev);
        }
        out[(size_t)br * Btot + rowg0 + row] = fmaf(ev, pw, pb);
    }
}

extern "C" void kernel_launch(void* const* d_in, const int* in_sizes, int n_in,
                              void* d_out, int out_size)
{
    const int Btot = in_sizes[0] / 128;
    static bool attr_set = false;
    if (!attr_set) {
        cudaFuncSetAttribute(qmain, cudaFuncAttributeMaxDynamicSharedMemorySize, SMEM_BYTES);
        attr_set = true;
    }
    qprep<<<80, 256>>>((const float*)d_in[2], (const float*)d_in[6]);
    qcirc<<<1, 512>>>((const float*)d_in[10], (const float*)d_in[11]);
    qmain<<<Btot / TB, NT, SMEM_BYTES>>>(
        (const float*)d_in[0],  (const float*)d_in[1],
        (const float*)d_in[3],  (const float*)d_in[4],  (const float*)d_in[5],
        (const float*)d_in[7],  (const float*)d_in[8],  (const float*)d_in[9],
        (const float*)d_in[12], (const float*)d_in[13],
        (const float*)d_in[14], (const float*)d_in[15],
        (float*)d_out, Btot);
}

// round 11
// speedup vs baseline: 4.7310x; 1.0199x over previous
#include <cuda_runtime.h>
#include <cuda_fp16.h>
#include <math.h>
#include <stdint.h>

#define NT 256
#define TB 128
#define KDIM 160
#define RS 168           // k-stride (elements)

// smem byte offsets
#define OFF_A   0                 // fp16 [128][168] = 43008
#define OFF_B   43008             // [buf][64][168] fp16 : 2 x 21504
#define OFF_QIN 86016             // float [2][128][4]
#define OFF_B1  90112             // float [2][256]
#define OFF_W2F 92160             // uint2 [2][16][32] packed W2 B-frags = 8192
#define OFF_B2  100352            // float [2][4]
#define OFF_A16 100384            // float [2][16][16] quadratic-form matrices
#define OFF_PP  102432
#define SMEM_BYTES 102448

#define BCH  21504       // bytes per N=64 chunk (64 x 168 x 2B)

// W1 as fp16, [br][n][RS]
__device__ __align__(16) __half g_W1h[2][256][RS];
// quadratic-form matrices A = Re(U^T Z0 U), [br][i][j]
__device__ float g_A[2][16][16];

__device__ __forceinline__ uint32_t smem_u32(const void* p) {
    uint32_t a;
    asm("{ .reg .u64 t; cvta.to.shared.u64 t, %1; cvt.u32.u64 %0, t; }" : "=r"(a) : "l"(p));
    return a;
}
__device__ __forceinline__ void mma_f16(float (&d)[4], const uint32_t (&a)[4],
                                        uint32_t b0, uint32_t b1) {
    asm volatile(
        "mma.sync.aligned.m16n8k16.row.col.f32.f16.f16.f32 "
        "{%0,%1,%2,%3}, {%4,%5,%6,%7}, {%8,%9}, {%0,%1,%2,%3};"
        : "+f"(d[0]), "+f"(d[1]), "+f"(d[2]), "+f"(d[3])
        : "r"(a[0]), "r"(a[1]), "r"(a[2]), "r"(a[3]), "r"(b0), "r"(b1));
}
__device__ __forceinline__ void mma_f16u(float (&d)[4], uint32_t a0, uint32_t a1,
                                         uint32_t a2, uint32_t a3,
                                         uint32_t b0, uint32_t b1) {
    asm volatile(
        "mma.sync.aligned.m16n8k16.row.col.f32.f16.f16.f32 "
        "{%0,%1,%2,%3}, {%4,%5,%6,%7}, {%8,%9}, {%0,%1,%2,%3};"
        : "+f"(d[0]), "+f"(d[1]), "+f"(d[2]), "+f"(d[3])
        : "r"(a0), "r"(a1), "r"(a2), "r"(a3), "r"(b0), "r"(b1));
}
__device__ __forceinline__ void ldsm4(uint32_t (&r)[4], uint32_t addr) {
    asm volatile("ldmatrix.sync.aligned.m8n8.x4.shared.b16 {%0,%1,%2,%3}, [%4];"
        : "=r"(r[0]), "=r"(r[1]), "=r"(r[2]), "=r"(r[3]) : "r"(addr));
}
__device__ __forceinline__ uint32_t h2u(float a, float b) {
    __half2 h = __floats2half2_rn(a, b);
    return *(uint32_t*)&h;
}
#define CPA16(dst, src) asm volatile("cp.async.cg.shared.global [%0], [%1], 16;" :: "r"(dst), "l"(src))
#define CPA_COMMIT()    asm volatile("cp.async.commit_group;")
#define CPA_WAIT1()     asm volatile("cp.async.wait_group 1;")
#define CPA_WAIT0()     asm volatile("cp.async.wait_group 0;")

// ---------------- quantum gates on 16-amplitude register state ----------------
template<int M>
__device__ __forceinline__ void g_ry(float (&ar)[16], float (&ai)[16], float c, float s) {
#pragma unroll
    for (int i = 0; i < 16; i++) if (!(i & M)) {
        const int j = i | M;
        float xr = ar[i], xi = ai[i], yr = ar[j], yi = ai[j];
        ar[i] = c * xr - s * yr;  ai[i] = c * xi - s * yi;
        ar[j] = s * xr + c * yr;  ai[j] = s * xi + c * yi;
    }
}
template<int M>
__device__ __forceinline__ void g_rx(float (&ar)[16], float (&ai)[16], float c, float s) {
#pragma unroll
    for (int i = 0; i < 16; i++) if (!(i & M)) {
        const int j = i | M;
        float xr = ar[i], xi = ai[i], yr = ar[j], yi = ai[j];
        ar[i] = c * xr + s * yi;   ai[i] = c * xi - s * yr;
        ar[j] = s * xi + c * yr;   ai[j] = -s * xr + c * yi;
    }
}
template<int M>
__device__ __forceinline__ void g_rz(float (&ar)[16], float (&ai)[16], float c, float s) {
#pragma unroll
    for (int i = 0; i < 16; i++) if (!(i & M)) {
        const int j = i | M;
        float xr = ar[i], xi = ai[i], yr = ar[j], yi = ai[j];
        ar[i] = c * xr + s * xi;   ai[i] = c * xi - s * xr;
        ar[j] = c * yr - s * yi;   ai[j] = c * yi + s * yr;
    }
}
template<int MC, int MT>
__device__ __forceinline__ void g_cnot(float (&ar)[16], float (&ai)[16]) {
#pragma unroll
    for (int i = 0; i < 16; i++) if ((i & MC) && !(i & MT)) {
        const int j = i | MT;
        float tr = ar[i]; ar[i] = ar[j]; ar[j] = tr;
        float ti = ai[i]; ai[i] = ai[j]; ai[j] = ti;
    }
}

// ---------------- merged prep: W1 -> fp16 (blocks 0..79) + circuit A (block 80) ----
__global__ void qpre(const float* __restrict__ W1a, const float* __restrict__ W1b,
                     const float* __restrict__ qwa, const float* __restrict__ qwb) {
    if (blockIdx.x < 80) {
        const int t = blockIdx.x * 256 + threadIdx.x;    // 0..20479
        const int br = t / 10240;
        const int rem = t % 10240;
        const int n = rem / 40, k4 = rem % 40;
        const float4 v = *(const float4*)((br ? W1b : W1a) + (size_t)n * KDIM + k4 * 4);
        __half2* dst = (__half2*)&g_W1h[br][n][k4 * 4];
        dst[0] = __floats2half2_rn(v.x, v.y);
        dst[1] = __floats2half2_rn(v.z, v.w);
        return;
    }
    // ---- block 80: fixed-circuit unitary -> quadratic form A (256 threads) ----
    __shared__ float Ur[2][16][16], Ui[2][16][16];   // [br][k][col]
    const int tid = threadIdx.x;
    if (tid < 32) {
        const int br = tid >> 4, col = tid & 15;
        const float* qw = br ? qwb : qwa;
        float trc[24], trs[24];
#pragma unroll
        for (int g = 0; g < 24; g++) sincosf(0.5f * qw[g], &trs[g], &trc[g]);
        float ar[16], ai[16];
#pragma unroll
        for (int i = 0; i < 16; i++) { ar[i] = (i == col) ? 1.f : 0.f; ai[i] = 0.f; }
#pragma unroll
        for (int l = 0; l < 2; l++) {
            const int lb = l * 12;
            g_rx<8>(ar, ai, trc[lb + 0],  trs[lb + 0]);
            g_ry<8>(ar, ai, trc[lb + 1],  trs[lb + 1]);
            g_rz<8>(ar, ai, trc[lb + 2],  trs[lb + 2]);
            g_rx<4>(ar, ai, trc[lb + 3],  trs[lb + 3]);
            g_ry<4>(ar, ai, trc[lb + 4],  trs[lb + 4]);
            g_rz<4>(ar, ai, trc[lb + 5],  trs[lb + 5]);
            g_rx<2>(ar, ai, trc[lb + 6],  trs[lb + 6]);
            g_ry<2>(ar, ai, trc[lb + 7],  trs[lb + 7]);
            g_rz<2>(ar, ai, trc[lb + 8],  trs[lb + 8]);
            g_rx<1>(ar, ai, trc[lb + 9],  trs[lb + 9]);
            g_ry<1>(ar, ai, trc[lb + 10], trs[lb + 10]);
            g_rz<1>(ar, ai, trc[lb + 11], trs[lb + 11]);
            g_cnot<8, 4>(ar, ai);
            g_cnot<4, 2>(ar, ai);
            g_cnot<2, 1>(ar, ai);
            g_cnot<1, 8>(ar, ai);
        }
#pragma unroll
        for (int k = 0; k < 16; k++) { Ur[br][k][col] = ar[k]; Ui[br][k][col] = ai[k]; }
    }
    __syncthreads();
#pragma unroll
    for (int e = 0; e < 2; e++) {
        const int idx = e * 256 + tid;                 // 0..511
        const int br = idx >> 8, rem2 = idx & 255;
        const int i = rem2 >> 4, j = rem2 & 15;
        float s = 0.f;
#pragma unroll
        for (int k = 0; k < 16; k++) {
            const float z = (k & 8) ? -1.f : 1.f;
            s += z * (Ur[br][k][i] * Ur[br][k][j] + Ui[br][k][i] * Ui[br][k][j]);
        }
        g_A[br][i][j] = s;
    }
}

// ---------------- main kernel ----------------
__global__ __launch_bounds__(NT, 2)
void qmain(const float* __restrict__ state, const float* __restrict__ action,
           const float* __restrict__ b1a, const float* __restrict__ W2a, const float* __restrict__ b2a,
           const float* __restrict__ b1b, const float* __restrict__ W2b, const float* __restrict__ b2b,
           const float* __restrict__ pwa, const float* __restrict__ pba,
           const float* __restrict__ pwb, const float* __restrict__ pbb,
           float* __restrict__ out, int Btot)
{
    extern __shared__ __align__(16) unsigned char smp[];
    float* smf = (float*)smp;
    __half* Ah = (__half*)(smp + OFF_A);
    float* qin = smf + OFF_QIN / 4;
    const uint32_t smb = smem_u32(smp);

    const int tid = threadIdx.x;
    const int lane = tid & 31, w = tid >> 5;
    const int gid = lane >> 2, tig = lane & 3;
    const int wm = w & 3, wn = w >> 2;
    const int m0 = wm * 32, n0 = wn * 32;
    const int rowg0 = blockIdx.x * TB;

    // ---- kick off B load for pass 0 (buf 0) ----
    {
        const char* sH = (const char*)&g_W1h[0][0][0];
        for (int i = tid; i < BCH / 16; i += NT)
            CPA16(smb + OFF_B + i * 16, sH + i * 16);
        CPA_COMMIT();
    }

    // ---- params into smem ----
    for (int i = tid; i < 512; i += NT)
        smf[OFF_B1 / 4 + i] = ((i >> 8) ? b1b : b1a)[i & 255];
    // W2 packed as per-lane B-fragments: [br][group(16 cols)][lane] -> 2 u32
    for (int i = tid; i < 1024; i += NT) {
        const int br = i >> 9, g = (i >> 5) & 15, ln = i & 31;
        const int gq = ln >> 2, gt = ln & 3;
        const int kc = g * 16 + 2 * gt;
        const float* W2 = br ? W2b : W2a;
        uint32_t r0 = 0, r1 = 0;
        if (gq < 4) {
            r0 = h2u(W2[gq * 256 + kc],     W2[gq * 256 + kc + 1]);
            r1 = h2u(W2[gq * 256 + kc + 8], W2[gq * 256 + kc + 9]);
        }
        ((uint2*)(smp + OFF_W2F))[i] = make_uint2(r0, r1);
    }
    if (tid < 8)  smf[OFF_B2 / 4 + tid] = ((tid >> 2) ? b2b : b2a)[tid & 3];
    for (int i = tid; i < 512; i += NT)
        smf[OFF_A16 / 4 + i] = ((const float*)g_A)[i];
    if (tid < 4)
        smf[OFF_PP / 4 + tid] = (tid == 0) ? pwa[0] : (tid == 1) ? pba[0]
                               : (tid == 2) ? pwb[0] : pbb[0];
    for (int i = tid; i < 1024; i += NT) qin[i] = 0.f;

    // ---- x -> fp16 A tile [row][k], stride RS ----
    {
        const int r = tid >> 1, hf = tid & 1;
        const float* srow = state  + (size_t)(rowg0 + r) * 128;
        const float* arow = action + (size_t)(rowg0 + r) * 32;
#pragma unroll 5
        for (int i = 0; i < 20; i++) {
            const int k = hf * 80 + i * 4;
            const float4 v = (k < 128) ? *(const float4*)(srow + k)
                                       : *(const float4*)(arow + (k - 128));
            *(__half2*)(Ah + r * RS + k)     = __floats2half2_rn(v.x, v.y);
            *(__half2*)(Ah + r * RS + k + 2) = __floats2half2_rn(v.z, v.w);
        }
    }
    __syncthreads();

    // ---- ldmatrix byte-address bases ----
    const uint32_t aB0 = smb + OFF_A
        + (uint32_t)((m0 + (lane & 15)) * RS + 8 * (lane >> 4)) * 2;
    const uint32_t aB1 = aB0 + 16u * RS * 2;
    const uint32_t bO0 = (uint32_t)((n0 + 8 * (lane >> 4) + (lane & 7)) * RS
                                    + 8 * ((lane >> 3) & 1)) * 2;
    const uint32_t bO1 = bO0 + 16u * RS * 2;

    // q partial accumulators (tensor-core epilogue), per mf fragment
    float qacc[2][4];
#pragma unroll
    for (int mf = 0; mf < 2; mf++)
#pragma unroll
        for (int c = 0; c < 4; c++) qacc[mf][c] = 0.f;

#pragma unroll 1
    for (int pass = 0; pass < 8; pass++) {
        const int br = pass >> 2, chunk = pass & 3;
        const int nbase = chunk * 64;
        const int buf = pass & 1;

        // prefetch next chunk into other buffer
        if (pass < 7) {
            const int pN = pass + 1;
            const char* sH = (const char*)&g_W1h[pN >> 2][(pN & 3) * 64][0];
            const uint32_t dst = smb + OFF_B + (uint32_t)(pN & 1) * BCH;
            for (int i = tid; i < BCH / 16; i += NT)
                CPA16(dst + i * 16, sH + i * 16);
            CPA_COMMIT();
            CPA_WAIT1();
        } else {
            CPA_WAIT0();
        }
        __syncthreads();

        const uint32_t bB = smb + OFF_B + (uint32_t)buf * BCH;

        float acc[2][4][4];
#pragma unroll
        for (int mf = 0; mf < 2; mf++)
#pragma unroll
            for (int nf = 0; nf < 4; nf++)
#pragma unroll
                for (int c = 0; c < 4; c++) acc[mf][nf][c] = 0.f;

#pragma unroll
        for (int ks = 0; ks < 10; ks++) {
            const uint32_t kb = (uint32_t)(ks * 32);   // 16 elem * 2B
            uint32_t af[2][4], bf[2][4];
            ldsm4(af[0], aB0 + kb);
            ldsm4(af[1], aB1 + kb);
            ldsm4(bf[0], bB + bO0 + kb);
            ldsm4(bf[1], bB + bO1 + kb);
#pragma unroll
            for (int g = 0; g < 2; g++)
#pragma unroll
                for (int h = 0; h < 2; h++)
#pragma unroll
                    for (int mf = 0; mf < 2; mf++)
                        mma_f16(acc[mf][g * 2 + h], af[mf], bf[g][h * 2], bf[g][h * 2 + 1]);
        }

        // ---- tensor-core epilogue: bias+relu -> fp16 frags -> MMA vs W2 frags ----
        {
            const float2* b1v = (const float2*)(smf + OFF_B1 / 4 + br * 256);
            const uint2* w2f = (const uint2*)(smp + OFF_W2F);
            const int gbase = (nbase + n0) >> 4;
            const uint2 bfA = w2f[(((br << 4) + gbase) << 5) + lane];
            const uint2 bfB = w2f[(((br << 4) + gbase + 1) << 5) + lane];
#pragma unroll
            for (int ks = 0; ks < 2; ks++) {
                const int nfa = ks * 2, nfb = nfa + 1;
                const float2 bba = b1v[((nbase + n0 + nfa * 8) >> 1) + tig];
                const float2 bbb = b1v[((nbase + n0 + nfb * 8) >> 1) + tig];
                const uint2 bfr = ks ? bfB : bfA;
#pragma unroll
                for (int mf = 0; mf < 2; mf++) {
                    const uint32_t a0 = h2u(fmaxf(acc[mf][nfa][0] + bba.x, 0.f),
                                            fmaxf(acc[mf][nfa][1] + bba.y, 0.f));
                    const uint32_t a1 = h2u(fmaxf(acc[mf][nfa][2] + bba.x, 0.f),
                                            fmaxf(acc[mf][nfa][3] + bba.y, 0.f));
                    const uint32_t a2 = h2u(fmaxf(acc[mf][nfb][0] + bbb.x, 0.f),
                                            fmaxf(acc[mf][nfb][1] + bbb.y, 0.f));
                    const uint32_t a3 = h2u(fmaxf(acc[mf][nfb][2] + bbb.x, 0.f),
                                            fmaxf(acc[mf][nfb][3] + bbb.y, 0.f));
                    mma_f16u(qacc[mf], a0, a1, a2, a3, bfr.x, bfr.y);
                }
            }
        }

        // flush q partials at branch boundary
        if (chunk == 3) {
            if (tig < 2) {
                const int qb = 2 * tig;
#pragma unroll
                for (int mf = 0; mf < 2; mf++) {
                    float* q0 = qin + ((br << 7) + m0 + mf * 16 + gid) * 4 + qb;
                    float* q1 = qin + ((br << 7) + m0 + mf * 16 + gid + 8) * 4 + qb;
                    atomicAdd(q0,     qacc[mf][0]);
                    atomicAdd(q0 + 1, qacc[mf][1]);
                    atomicAdd(q1,     qacc[mf][2]);
                    atomicAdd(q1 + 1, qacc[mf][3]);
                }
            }
#pragma unroll
            for (int mf = 0; mf < 2; mf++)
#pragma unroll
                for (int c = 0; c < 4; c++) qacc[mf][c] = 0.f;
        }

        __syncthreads();   // all reads of buf done before overwrite
    }
    __syncthreads();

    // ---- quadratic-form epilogue: 1 row/thread, 128 rows x 2 branches ----
    {
        const int br = tid >> 7, row = tid & 127;
        const float* b2s = smf + OFF_B2 / 4 + br * 4;
        const float* Ab = smf + OFF_A16 / 4 + br * 256;
        const float pw = smf[OFF_PP / 4 + br * 2];
        const float pb = smf[OFF_PP / 4 + br * 2 + 1];
        const float* qv = qin + ((br << 7) + row) * 4;

        float c[4], s[4];
#pragma unroll
        for (int q = 0; q < 4; q++)
            sincosf(0.5f * (qv[q] + b2s[q]), &s[q], &c[q]);

        // v[i]: bit3=qubit0 ... bit0=qubit3
        float p01[4] = {c[0] * c[1], c[0] * s[1], s[0] * c[1], s[0] * s[1]};
        float p23[4] = {c[2] * c[3], c[2] * s[3], s[2] * c[3], s[2] * s[3]};
        float v[16];
#pragma unroll
        for (int hi = 0; hi < 4; hi++)
#pragma unroll
            for (int lo = 0; lo < 4; lo++)
                v[hi * 4 + lo] = p01[hi] * p23[lo];

        float ev = 0.f;
#pragma unroll
        for (int i = 0; i < 16; i++) {
            const float4* Ar = (const float4*)(Ab + i * 16);
            float wi = 0.f;
#pragma unroll
            for (int j4 = 0; j4 < 4; j4++) {
                const float4 a4 = Ar[j4];
                wi = fmaf(a4.x, v[j4 * 4 + 0], wi);
                wi = fmaf(a4.y, v[j4 * 4 + 1], wi);
                wi = fmaf(a4.z, v[j4 * 4 + 2], wi);
                wi = fmaf(a4.w, v[j4 * 4 + 3], wi);
            }
            ev = fmaf(v[i], wi, ev);
        }
        out[(size_t)br * Btot + rowg0 + row] = fmaf(ev, pw, pb);
    }
}

extern "C" void kernel_launch(void* const* d_in, const int* in_sizes, int n_in,
                              void* d_out, int out_size)
{
    const int Btot = in_sizes[0] / 128;
    static bool attr_set = false;
    if (!attr_set) {
        cudaFuncSetAttribute(qmain, cudaFuncAttributeMaxDynamicSharedMemorySize, SMEM_BYTES);
        attr_set = true;
    }
    qpre<<<81, 256>>>((const float*)d_in[2], (const float*)d_in[6],
                      (const float*)d_in[10], (const float*)d_in[11]);
    qmain<<<Btot / TB, NT, SMEM_BYTES>>>(
        (const float*)d_in[0],  (const float*)d_in[1],
        (const float*)d_in[3],  (const float*)d_in[4],  (const float*)d_in[5],
        (const float*)d_in[7],  (const float*)d_in[8],  (const float*)d_in[9],
        (const float*)d_in[12], (const float*)d_in[13],
        (const float*)d_in[14], (const float*)d_in[15],
        (float*)d_out, Btot);
}